// round 10
// baseline (speedup 1.0000x reference)
#include <cuda_runtime.h>
#include <cstdint>

#define BATCH   2048
#define DMODEL  2048
#define DSTATE  16
#define DEVENT  32

// ---------------- scratch ----------------
__device__ float g_delta[BATCH * DMODEL];   // delta_safe
__device__ float g_pole [BATCH * DMODEL];   // event @ A_We.T
__device__ float g_Abase[DMODEL * DSTATE];  // -exp(clip(A_log,-3,1))
__device__ float g_Bt   [BATCH * DSTATE];
__device__ float g_Ct   [BATCH * DSTATE];
__device__ float g_partH[4][BATCH * 2 * DSTATE];  // split-K partials of x@B_W1.T
__device__ float g_partC[4][BATCH * DSTATE];      // split-K partials of x@C_W.T

// ---------------- helpers ----------------
__device__ __forceinline__ void mma_tf32(float* c, const uint32_t* a, const uint32_t* b) {
    asm volatile(
        "mma.sync.aligned.m16n8k8.row.col.f32.tf32.tf32.f32 "
        "{%0,%1,%2,%3},{%4,%5,%6,%7},{%8,%9},{%0,%1,%2,%3};"
        : "+f"(c[0]), "+f"(c[1]), "+f"(c[2]), "+f"(c[3])
        : "r"(a[0]), "r"(a[1]), "r"(a[2]), "r"(a[3]), "r"(b[0]), "r"(b[1]));
}

__device__ __forceinline__ void cp16(float* dst, const float* src) {
    uint32_t d = (uint32_t)__cvta_generic_to_shared(dst);
    asm volatile("cp.async.cg.shared.global [%0],[%1],16;\n" :: "r"(d), "l"(src));
}
__device__ __forceinline__ void cp_commit() {
    asm volatile("cp.async.commit_group;\n");
}

// ---------------- kernel 1: pole = event @ A_We.T (+ A_base fold) ---------
__global__ __launch_bounds__(256) void k_pole(const float* __restrict__ Ev,
                                              const float* __restrict__ A_We,
                                              const float* __restrict__ A_log) {
    __shared__ float Es[32][33];
    __shared__ float Ws[128][33];
    int t  = threadIdx.x;
    int b0 = blockIdx.x * 32;
    int d0 = blockIdx.y * 128;

    // folded A_base: 64 blocks (y==0) x 256 thr x 2 elems = 32768
    if (blockIdx.y == 0) {
        int i = (blockIdx.x * 256 + t) * 2;
#pragma unroll
        for (int e = 0; e < 2; ++e) {
            float a = A_log[i + e];
            a = fminf(fmaxf(a, -3.0f), 1.0f);
            g_Abase[i + e] = -__expf(a);
        }
    }

    {
        int idx = t;
        int r = idx >> 3, c4 = idx & 7;
        float4 v = *(const float4*)(Ev + (size_t)(b0 + r) * DEVENT + c4 * 4);
        Es[r][c4 * 4 + 0] = v.x; Es[r][c4 * 4 + 1] = v.y;
        Es[r][c4 * 4 + 2] = v.z; Es[r][c4 * 4 + 3] = v.w;
    }
#pragma unroll
    for (int i = 0; i < 4; ++i) {
        int idx = t + i * 256;
        int r = idx >> 3, c4 = idx & 7;
        float4 v = *(const float4*)(A_We + (size_t)(d0 + r) * DEVENT + c4 * 4);
        Ws[r][c4 * 4 + 0] = v.x; Ws[r][c4 * 4 + 1] = v.y;
        Ws[r][c4 * 4 + 2] = v.z; Ws[r][c4 * 4 + 3] = v.w;
    }
    __syncthreads();

    int d_sub = t & 127;
    int half  = t >> 7;
    for (int bs = half; bs < 32; bs += 2) {
        float acc = 0.0f;
#pragma unroll
        for (int e = 0; e < 32; ++e) acc += Es[bs][e] * Ws[d_sub][e];
        g_pole[(size_t)(b0 + bs) * DMODEL + d0 + d_sub] = acc;
    }
}

// ---------------- kernel 2a: split-K partials of x@B_W1.T and x@C_W.T -----
__global__ __launch_bounds__(256) void k_small_p(
    const float* __restrict__ X,
    const float* __restrict__ B_W1, const float* __restrict__ C_W) {
    __shared__ float Xs[32][132];
    __shared__ float Ws[48][132];

    int t    = threadIdx.x;
    int b0   = blockIdx.x * 32;
    int kb   = blockIdx.y * 512;
    int row  = t >> 3;
    int tcol = t & 7;

    float accH[4] = {0, 0, 0, 0};
    float accC[2] = {0, 0};

    for (int kc = kb; kc < kb + 512; kc += 128) {
#pragma unroll
        for (int i = 0; i < 4; ++i) {
            int idx = t + i * 256;
            int r = idx >> 5, c4 = idx & 31;
            float4 v = *(const float4*)(X + (size_t)(b0 + r) * DMODEL + kc + c4 * 4);
            *(float4*)(&Xs[r][c4 * 4]) = v;
        }
#pragma unroll
        for (int i = 0; i < 6; ++i) {
            int idx = t + i * 256;
            int r = idx >> 5, c4 = idx & 31;
            const float* src = (r < 32)
                ? (B_W1 + (size_t)r * DMODEL + kc + c4 * 4)
                : (C_W + (size_t)(r - 32) * DMODEL + kc + c4 * 4);
            float4 v = *(const float4*)src;
            *(float4*)(&Ws[r][c4 * 4]) = v;
        }
        __syncthreads();
#pragma unroll 4
        for (int kk = 0; kk < 128; ++kk) {
            float xv = Xs[row][kk];
#pragma unroll
            for (int i = 0; i < 4; ++i) accH[i] += xv * Ws[tcol + 8 * i][kk];
#pragma unroll
            for (int i = 0; i < 2; ++i) accC[i] += xv * Ws[32 + tcol + 8 * i][kk];
        }
        __syncthreads();
    }

    int ks = blockIdx.y;
#pragma unroll
    for (int i = 0; i < 4; ++i)
        g_partH[ks][(size_t)(b0 + row) * 32 + tcol + 8 * i] = accH[i];
#pragma unroll
    for (int i = 0; i < 2; ++i)
        g_partC[ks][(size_t)(b0 + row) * DSTATE + tcol + 8 * i] = accC[i];
}

// ---------------- kernel 2b: combine partials, silu, B_t / C_t ------------
__global__ __launch_bounds__(256) void k_small_f(
    const float* __restrict__ Ev,
    const float* __restrict__ B_b1, const float* __restrict__ B_W2,
    const float* __restrict__ B_b2, const float* __restrict__ B_We) {
    __shared__ float Hs[32][33];

    int t    = threadIdx.x;
    int b0   = blockIdx.x * 32;
    int row  = t >> 3;
    int tcol = t & 7;

#pragma unroll
    for (int i = 0; i < 4; ++i) {
        int j = tcol + 8 * i;
        size_t off = (size_t)(b0 + row) * 32 + j;
        float z = g_partH[0][off] + g_partH[1][off]
                + g_partH[2][off] + g_partH[3][off] + B_b1[j];
        Hs[row][j] = z / (1.0f + __expf(-z));
    }
#pragma unroll
    for (int i = 0; i < 2; ++i) {
        int n = tcol + 8 * i;
        size_t off = (size_t)(b0 + row) * DSTATE + n;
        g_Ct[off] = g_partC[0][off] + g_partC[1][off]
                  + g_partC[2][off] + g_partC[3][off];
    }
    __syncthreads();

    for (int o = t; o < 32 * 16; o += 256) {
        int r = o >> 4, n = o & 15;
        float acc = B_b2[n];
#pragma unroll
        for (int j = 0; j < 32; ++j) acc += Hs[r][j] * B_W2[n * 32 + j];
#pragma unroll
        for (int e = 0; e < 32; ++e) acc += Ev[(size_t)(b0 + r) * DEVENT + e] * B_We[n * 32 + e];
        g_Bt[(size_t)(b0 + r) * DSTATE + n] = acc;
    }
}

// ---------------- kernel 3: delta GEMM, cp.async double-buffered ----------
#define STG 4608  // 128*36 floats per operand per stage

__global__ __launch_bounds__(256) void k_gemm_delta(
    const float* __restrict__ X, const float* __restrict__ Wd,
    const float* __restrict__ Ev, const float* __restrict__ We,
    const float* __restrict__ bd) {
    extern __shared__ float smbuf[];
    float* As = smbuf;            // [2][128][36]
    float* Bs = smbuf + 2 * STG;  // [2][128][36]

    const int tid  = threadIdx.x;
    const int row0 = blockIdx.y * 128;   // batch
    const int col0 = blockIdx.x * 128;   // d_model
    const int wid  = tid >> 5, lane = tid & 31;
    const int g    = lane >> 2, tg = lane & 3;
    const int wm0  = (wid & 1) * 64;
    const int wn0  = (wid >> 1) * 32;

    float acc[4][4][4];
#pragma unroll
    for (int mi = 0; mi < 4; ++mi)
#pragma unroll
        for (int ni = 0; ni < 4; ++ni)
#pragma unroll
            for (int r = 0; r < 4; ++r) acc[mi][ni][r] = 0.0f;

    auto load_tile = [&](int kt, int s) {
        const float *srcA, *srcB;
        int lda, ldb;
        if (kt < 64) {
            srcA = X  + (size_t)row0 * DMODEL + kt * 32; lda = DMODEL;
            srcB = Wd + (size_t)col0 * DMODEL + kt * 32; ldb = DMODEL;
        } else {
            srcA = Ev + (size_t)row0 * DEVENT; lda = DEVENT;
            srcB = We + (size_t)col0 * DEVENT; ldb = DEVENT;
        }
        float* as = As + s * STG;
        float* bs = Bs + s * STG;
#pragma unroll
        for (int i = 0; i < 4; ++i) {
            int idx = tid + i * 256;     // 1024 16B chunks per operand
            int m = idx >> 3, k4 = idx & 7;
            cp16(as + m * 36 + k4 * 4, srcA + (size_t)m * lda + k4 * 4);
            cp16(bs + m * 36 + k4 * 4, srcB + (size_t)m * ldb + k4 * 4);
        }
    };

    load_tile(0, 0);
    cp_commit();

    for (int kt = 0; kt < 65; ++kt) {
        if (kt < 64) {
            load_tile(kt + 1, (kt + 1) & 1);
            cp_commit();
            asm volatile("cp.async.wait_group 1;\n");
        } else {
            asm volatile("cp.async.wait_group 0;\n");
        }
        __syncthreads();

        const float* as = As + (kt & 1) * STG;
        const float* bs = Bs + (kt & 1) * STG;
#pragma unroll
        for (int ks = 0; ks < 4; ++ks) {
            uint32_t a[4][4], b[4][2];
            int k = ks * 8 + tg;
#pragma unroll
            for (int mi = 0; mi < 4; ++mi) {
                int m = wm0 + mi * 16;
                a[mi][0] = __float_as_uint(as[(m + g) * 36 + k]);
                a[mi][1] = __float_as_uint(as[(m + g + 8) * 36 + k]);
                a[mi][2] = __float_as_uint(as[(m + g) * 36 + k + 4]);
                a[mi][3] = __float_as_uint(as[(m + g + 8) * 36 + k + 4]);
            }
#pragma unroll
            for (int ni = 0; ni < 4; ++ni) {
                int n = wn0 + ni * 8 + g;
                b[ni][0] = __float_as_uint(bs[n * 36 + k]);
                b[ni][1] = __float_as_uint(bs[n * 36 + k + 4]);
            }
#pragma unroll
            for (int mi = 0; mi < 4; ++mi)
#pragma unroll
                for (int ni = 0; ni < 4; ++ni)
                    mma_tf32(acc[mi][ni], a[mi], b[ni]);
        }
        __syncthreads();
    }

    // epilogue: delta_safe = min(softplus(z + bd), 2)
#pragma unroll
    for (int mi = 0; mi < 4; ++mi) {
        int rbase = row0 + wm0 + mi * 16 + g;
#pragma unroll
        for (int ni = 0; ni < 4; ++ni) {
            int cbase = col0 + wn0 + ni * 8 + tg * 2;
#pragma unroll
            for (int r = 0; r < 4; ++r) {
                int bb = rbase + (r >> 1) * 8;
                int dd = cbase + (r & 1);
                float z = acc[mi][ni][r] + __ldg(&bd[dd]);
                float sp = fmaxf(z, 0.0f) + __logf(1.0f + __expf(-fabsf(z)));
                g_delta[(size_t)bb * DMODEL + dd] = fminf(sp, 2.0f);
            }
        }
    }
}

// ---------------- kernel 4: state update, 2 quarter-tasks per thread ------
// Same 4-lane-per-pair coalesced layout; each thread additionally handles a
// second independent task at +half-grid offset, loads front-batched for MLP.
__global__ __launch_bounds__(256) void k_state(
    const float* __restrict__ X, const float* __restrict__ Hprev,
    const float* __restrict__ Dv, float* __restrict__ Yout,
    float* __restrict__ Hout) {
    const size_t HALF = (size_t)BATCH * DMODEL * 2;  // quarter-tasks per half
    size_t i0 = (size_t)blockIdx.x * 256 + threadIdx.x;
    size_t i1 = i0 + HALF;

    int pair0 = (int)(i0 >> 2), q0 = (int)(i0 & 3);
    int pair1 = (int)(i1 >> 2), q1 = (int)(i1 & 3);
    int b0 = pair0 >> 11, d0 = pair0 & 2047;
    int b1 = pair1 >> 11, d1 = pair1 & 2047;

    // front-batched loads (independent -> high MLP)
    float de0 = g_delta[pair0], de1 = g_delta[pair1];
    float po0 = g_pole [pair0], po1 = g_pole [pair1];
    float xv0 = X[pair0],       xv1 = X[pair1];

    float4 hpA = ((const float4*)Hprev)[(size_t)pair0 * 4 + q0];
    float4 hpB = ((const float4*)Hprev)[(size_t)pair1 * 4 + q1];
    float4 abA = ((const float4*)g_Abase)[d0 * 4 + q0];
    float4 abB = ((const float4*)g_Abase)[d1 * 4 + q1];
    float4 btA = ((const float4*)g_Bt)[b0 * 4 + q0];
    float4 btB = ((const float4*)g_Bt)[b1 * 4 + q1];
    float4 ctA = ((const float4*)g_Ct)[b0 * 4 + q0];
    float4 ctB = ((const float4*)g_Ct)[b1 * 4 + q1];

    float dbx0 = de0 * xv0, dbx1 = de1 * xv1;

    float4 hA;
    hA.x = __expf(de0 * (abA.x + po0)) * hpA.x + dbx0 * btA.x;
    hA.y = __expf(de0 * (abA.y + po0)) * hpA.y + dbx0 * btA.y;
    hA.z = __expf(de0 * (abA.z + po0)) * hpA.z + dbx0 * btA.z;
    hA.w = __expf(de0 * (abA.w + po0)) * hpA.w + dbx0 * btA.w;
    ((float4*)Hout)[(size_t)pair0 * 4 + q0] = hA;

    float4 hB;
    hB.x = __expf(de1 * (abB.x + po1)) * hpB.x + dbx1 * btB.x;
    hB.y = __expf(de1 * (abB.y + po1)) * hpB.y + dbx1 * btB.y;
    hB.z = __expf(de1 * (abB.z + po1)) * hpB.z + dbx1 * btB.z;
    hB.w = __expf(de1 * (abB.w + po1)) * hpB.w + dbx1 * btB.w;
    ((float4*)Hout)[(size_t)pair1 * 4 + q1] = hB;

    float pA = hA.x * ctA.x + hA.y * ctA.y + hA.z * ctA.z + hA.w * ctA.w;
    float pB = hB.x * ctB.x + hB.y * ctB.y + hB.z * ctB.z + hB.w * ctB.w;
    pA += __shfl_xor_sync(0xffffffff, pA, 1);
    pA += __shfl_xor_sync(0xffffffff, pA, 2);
    pB += __shfl_xor_sync(0xffffffff, pB, 1);
    pB += __shfl_xor_sync(0xffffffff, pB, 2);
    if (q0 == 0) Yout[pair0] = pA + Dv[d0] * xv0;
    if (q1 == 0) Yout[pair1] = pB + Dv[d1] * xv1;
}

// ---------------- launch (serial, single stream) ----------------
extern "C" void kernel_launch(void* const* d_in, const int* in_sizes, int n_in,
                              void* d_out, int out_size) {
    const float* x      = (const float*)d_in[0];
    const float* h_prev = (const float*)d_in[1];
    const float* ev     = (const float*)d_in[2];
    const float* A_log  = (const float*)d_in[3];
    const float* Dv     = (const float*)d_in[4];
    const float* Wd     = (const float*)d_in[5];
    const float* bd     = (const float*)d_in[6];
    const float* We     = (const float*)d_in[7];
    const float* B_W1   = (const float*)d_in[8];
    const float* B_b1   = (const float*)d_in[9];
    const float* B_W2   = (const float*)d_in[10];
    const float* B_b2   = (const float*)d_in[11];
    const float* B_We   = (const float*)d_in[12];
    const float* A_We   = (const float*)d_in[13];
    const float* C_W    = (const float*)d_in[14];

    float* y_out = (float*)d_out;
    float* h_out = y_out + (size_t)BATCH * DMODEL;

    const int gemm_smem = 4 * STG * (int)sizeof(float);  // 73728 B
    cudaFuncSetAttribute(k_gemm_delta,
                         cudaFuncAttributeMaxDynamicSharedMemorySize, gemm_smem);

    k_pole<<<dim3(BATCH / 32, DMODEL / 128), 256>>>(ev, A_We, A_log);
    k_small_p<<<dim3(BATCH / 32, 4), 256>>>(x, B_W1, C_W);
    k_small_f<<<BATCH / 32, 256>>>(ev, B_b1, B_W2, B_b2, B_We);
    k_gemm_delta<<<dim3(DMODEL / 128, BATCH / 128), 256, gemm_smem>>>(
        x, Wd, ev, We, bd);
    k_state<<<(BATCH * DMODEL * 2) / 256, 256>>>(x, h_prev, Dv, y_out, h_out);
}

// round 11
// speedup vs baseline: 1.0720x; 1.0720x over previous
#include <cuda_runtime.h>
#include <cstdint>

#define BATCH   2048
#define DMODEL  2048
#define DSTATE  16
#define DEVENT  32

// ---------------- scratch ----------------
__device__ float g_delta[BATCH * DMODEL];   // delta_safe
__device__ float g_pole [BATCH * DMODEL];   // event @ A_We.T
__device__ float g_Abase[DMODEL * DSTATE];  // -exp(clip(A_log,-3,1))
__device__ float g_Bt   [BATCH * DSTATE];
__device__ float g_Ct   [BATCH * DSTATE];
__device__ float g_partH[4][BATCH * 2 * DSTATE];  // split-K partials of x@B_W1.T
__device__ float g_partC[4][BATCH * DSTATE];      // split-K partials of x@C_W.T

// ---------------- helpers ----------------
__device__ __forceinline__ void mma_tf32(float* c, const uint32_t* a, const uint32_t* b) {
    asm volatile(
        "mma.sync.aligned.m16n8k8.row.col.f32.tf32.tf32.f32 "
        "{%0,%1,%2,%3},{%4,%5,%6,%7},{%8,%9},{%0,%1,%2,%3};"
        : "+f"(c[0]), "+f"(c[1]), "+f"(c[2]), "+f"(c[3])
        : "r"(a[0]), "r"(a[1]), "r"(a[2]), "r"(a[3]), "r"(b[0]), "r"(b[1]));
}

__device__ __forceinline__ void ldsm4(uint32_t* r, uint32_t addr) {
    asm volatile(
        "ldmatrix.sync.aligned.m8n8.x4.shared.b16 {%0,%1,%2,%3}, [%4];"
        : "=r"(r[0]), "=r"(r[1]), "=r"(r[2]), "=r"(r[3]) : "r"(addr));
}

__device__ __forceinline__ void cp16(float* dst, const float* src) {
    uint32_t d = (uint32_t)__cvta_generic_to_shared(dst);
    asm volatile("cp.async.cg.shared.global [%0],[%1],16;\n" :: "r"(d), "l"(src));
}
__device__ __forceinline__ void cp_commit() {
    asm volatile("cp.async.commit_group;\n");
}

// ---------------- kernel 1: pole = event @ A_We.T (+ A_base fold) ---------
__global__ __launch_bounds__(256) void k_pole(const float* __restrict__ Ev,
                                              const float* __restrict__ A_We,
                                              const float* __restrict__ A_log) {
    __shared__ float Es[32][33];
    __shared__ float Ws[128][33];
    int t  = threadIdx.x;
    int b0 = blockIdx.x * 32;
    int d0 = blockIdx.y * 128;

    if (blockIdx.y == 0) {
        int i = (blockIdx.x * 256 + t) * 2;
#pragma unroll
        for (int e = 0; e < 2; ++e) {
            float a = A_log[i + e];
            a = fminf(fmaxf(a, -3.0f), 1.0f);
            g_Abase[i + e] = -__expf(a);
        }
    }

    {
        int idx = t;
        int r = idx >> 3, c4 = idx & 7;
        float4 v = *(const float4*)(Ev + (size_t)(b0 + r) * DEVENT + c4 * 4);
        Es[r][c4 * 4 + 0] = v.x; Es[r][c4 * 4 + 1] = v.y;
        Es[r][c4 * 4 + 2] = v.z; Es[r][c4 * 4 + 3] = v.w;
    }
#pragma unroll
    for (int i = 0; i < 4; ++i) {
        int idx = t + i * 256;
        int r = idx >> 3, c4 = idx & 7;
        float4 v = *(const float4*)(A_We + (size_t)(d0 + r) * DEVENT + c4 * 4);
        Ws[r][c4 * 4 + 0] = v.x; Ws[r][c4 * 4 + 1] = v.y;
        Ws[r][c4 * 4 + 2] = v.z; Ws[r][c4 * 4 + 3] = v.w;
    }
    __syncthreads();

    int d_sub = t & 127;
    int half  = t >> 7;
    for (int bs = half; bs < 32; bs += 2) {
        float acc = 0.0f;
#pragma unroll
        for (int e = 0; e < 32; ++e) acc += Es[bs][e] * Ws[d_sub][e];
        g_pole[(size_t)(b0 + bs) * DMODEL + d0 + d_sub] = acc;
    }
}

// ---------------- kernel 2a: split-K partials of x@B_W1.T and x@C_W.T -----
__global__ __launch_bounds__(256) void k_small_p(
    const float* __restrict__ X,
    const float* __restrict__ B_W1, const float* __restrict__ C_W) {
    __shared__ float Xs[32][132];
    __shared__ float Ws[48][132];

    int t    = threadIdx.x;
    int b0   = blockIdx.x * 32;
    int kb   = blockIdx.y * 512;
    int row  = t >> 3;
    int tcol = t & 7;

    float accH[4] = {0, 0, 0, 0};
    float accC[2] = {0, 0};

    for (int kc = kb; kc < kb + 512; kc += 128) {
#pragma unroll
        for (int i = 0; i < 4; ++i) {
            int idx = t + i * 256;
            int r = idx >> 5, c4 = idx & 31;
            float4 v = *(const float4*)(X + (size_t)(b0 + r) * DMODEL + kc + c4 * 4);
            *(float4*)(&Xs[r][c4 * 4]) = v;
        }
#pragma unroll
        for (int i = 0; i < 6; ++i) {
            int idx = t + i * 256;
            int r = idx >> 5, c4 = idx & 31;
            const float* src = (r < 32)
                ? (B_W1 + (size_t)r * DMODEL + kc + c4 * 4)
                : (C_W + (size_t)(r - 32) * DMODEL + kc + c4 * 4);
            float4 v = *(const float4*)src;
            *(float4*)(&Ws[r][c4 * 4]) = v;
        }
        __syncthreads();
#pragma unroll 4
        for (int kk = 0; kk < 128; ++kk) {
            float xv = Xs[row][kk];
#pragma unroll
            for (int i = 0; i < 4; ++i) accH[i] += xv * Ws[tcol + 8 * i][kk];
#pragma unroll
            for (int i = 0; i < 2; ++i) accC[i] += xv * Ws[32 + tcol + 8 * i][kk];
        }
        __syncthreads();
    }

    int ks = blockIdx.y;
#pragma unroll
    for (int i = 0; i < 4; ++i)
        g_partH[ks][(size_t)(b0 + row) * 32 + tcol + 8 * i] = accH[i];
#pragma unroll
    for (int i = 0; i < 2; ++i)
        g_partC[ks][(size_t)(b0 + row) * DSTATE + tcol + 8 * i] = accC[i];
}

// ---------------- kernel 2b: combine partials, silu, B_t / C_t ------------
__global__ __launch_bounds__(256) void k_small_f(
    const float* __restrict__ Ev,
    const float* __restrict__ B_b1, const float* __restrict__ B_W2,
    const float* __restrict__ B_b2, const float* __restrict__ B_We) {
    __shared__ float Hs[32][33];

    int t    = threadIdx.x;
    int b0   = blockIdx.x * 32;
    int row  = t >> 3;
    int tcol = t & 7;

#pragma unroll
    for (int i = 0; i < 4; ++i) {
        int j = tcol + 8 * i;
        size_t off = (size_t)(b0 + row) * 32 + j;
        float z = g_partH[0][off] + g_partH[1][off]
                + g_partH[2][off] + g_partH[3][off] + B_b1[j];
        Hs[row][j] = z / (1.0f + __expf(-z));
    }
#pragma unroll
    for (int i = 0; i < 2; ++i) {
        int n = tcol + 8 * i;
        size_t off = (size_t)(b0 + row) * DSTATE + n;
        g_Ct[off] = g_partC[0][off] + g_partC[1][off]
                  + g_partC[2][off] + g_partC[3][off];
    }
    __syncthreads();

    for (int o = t; o < 32 * 16; o += 256) {
        int r = o >> 4, n = o & 15;
        float acc = B_b2[n];
#pragma unroll
        for (int j = 0; j < 32; ++j) acc += Hs[r][j] * B_W2[n * 32 + j];
#pragma unroll
        for (int e = 0; e < 32; ++e) acc += Ev[(size_t)(b0 + r) * DEVENT + e] * B_We[n * 32 + e];
        g_Bt[(size_t)(b0 + r) * DSTATE + n] = acc;
    }
}

// ---------------- kernel 3: delta GEMM, cp.async + ldmatrix ---------------
#define STG 4608  // 128*36 floats per operand per stage

__global__ __launch_bounds__(256) void k_gemm_delta(
    const float* __restrict__ X, const float* __restrict__ Wd,
    const float* __restrict__ Ev, const float* __restrict__ We,
    const float* __restrict__ bd) {
    extern __shared__ float smbuf[];
    float* As = smbuf;            // [2][128][36]
    float* Bs = smbuf + 2 * STG;  // [2][128][36]

    const int tid  = threadIdx.x;
    const int row0 = blockIdx.y * 128;   // batch
    const int col0 = blockIdx.x * 128;   // d_model
    const int wid  = tid >> 5, lane = tid & 31;
    const int g    = lane >> 2, tg = lane & 3;
    const int wm0  = (wid & 1) * 64;
    const int wn0  = (wid >> 1) * 32;

    const uint32_t sAbase = (uint32_t)__cvta_generic_to_shared(As);
    const uint32_t sBbase = (uint32_t)__cvta_generic_to_shared(Bs);

    // ldmatrix per-lane row/col offsets
    // A x4: j=lane>>3: {rows+0,k},{rows+8,k},{rows+0,k+4},{rows+8,k+4}
    const int aRow = wm0 + ((lane >> 3) & 1) * 8 + (lane & 7);
    const int aCol = (lane >> 4) * 4;
    // B x4 (two ni at once): j: {n+0,k},{n+0,k+4},{n+8,k},{n+8,k+4}
    const int bRow = wn0 + (lane >> 4) * 8 + (lane & 7);
    const int bCol = ((lane >> 3) & 1) * 4;

    float acc[4][4][4];
#pragma unroll
    for (int mi = 0; mi < 4; ++mi)
#pragma unroll
        for (int ni = 0; ni < 4; ++ni)
#pragma unroll
            for (int r = 0; r < 4; ++r) acc[mi][ni][r] = 0.0f;

    auto load_tile = [&](int kt, int s) {
        const float *srcA, *srcB;
        int lda, ldb;
        if (kt < 64) {
            srcA = X  + (size_t)row0 * DMODEL + kt * 32; lda = DMODEL;
            srcB = Wd + (size_t)col0 * DMODEL + kt * 32; ldb = DMODEL;
        } else {
            srcA = Ev + (size_t)row0 * DEVENT; lda = DEVENT;
            srcB = We + (size_t)col0 * DEVENT; ldb = DEVENT;
        }
        float* as = As + s * STG;
        float* bs = Bs + s * STG;
#pragma unroll
        for (int i = 0; i < 4; ++i) {
            int idx = tid + i * 256;     // 1024 16B chunks per operand
            int m = idx >> 3, k4 = idx & 7;
            cp16(as + m * 36 + k4 * 4, srcA + (size_t)m * lda + k4 * 4);
            cp16(bs + m * 36 + k4 * 4, srcB + (size_t)m * ldb + k4 * 4);
        }
    };

    load_tile(0, 0);
    cp_commit();

    for (int kt = 0; kt < 65; ++kt) {
        if (kt < 64) {
            load_tile(kt + 1, (kt + 1) & 1);
            cp_commit();
            asm volatile("cp.async.wait_group 1;\n");
        } else {
            asm volatile("cp.async.wait_group 0;\n");
        }
        __syncthreads();

        const uint32_t sa = sAbase + (kt & 1) * STG * 4;
        const uint32_t sb = sBbase + (kt & 1) * STG * 4;
#pragma unroll
        for (int ks = 0; ks < 4; ++ks) {
            uint32_t a[4][4], b[4][2];
#pragma unroll
            for (int mi = 0; mi < 4; ++mi)
                ldsm4(a[mi], sa + (uint32_t)(((aRow + mi * 16) * 36
                                             + aCol + ks * 8) * 4));
#pragma unroll
            for (int np = 0; np < 2; ++np) {
                uint32_t r4[4];
                ldsm4(r4, sb + (uint32_t)(((bRow + np * 16) * 36
                                          + bCol + ks * 8) * 4));
                b[np * 2 + 0][0] = r4[0]; b[np * 2 + 0][1] = r4[1];
                b[np * 2 + 1][0] = r4[2]; b[np * 2 + 1][1] = r4[3];
            }
#pragma unroll
            for (int mi = 0; mi < 4; ++mi)
#pragma unroll
                for (int ni = 0; ni < 4; ++ni)
                    mma_tf32(acc[mi][ni], a[mi], b[ni]);
        }
        __syncthreads();
    }

    // epilogue: delta_safe = min(softplus(z + bd), 2)
#pragma unroll
    for (int mi = 0; mi < 4; ++mi) {
        int rbase = row0 + wm0 + mi * 16 + g;
#pragma unroll
        for (int ni = 0; ni < 4; ++ni) {
            int cbase = col0 + wn0 + ni * 8 + tg * 2;
#pragma unroll
            for (int r = 0; r < 4; ++r) {
                int bb = rbase + (r >> 1) * 8;
                int dd = cbase + (r & 1);
                float z = acc[mi][ni][r] + __ldg(&bd[dd]);
                float sp = fmaxf(z, 0.0f) + __logf(1.0f + __expf(-fabsf(z)));
                g_delta[(size_t)bb * DMODEL + dd] = fminf(sp, 2.0f);
            }
        }
    }
}

// ---------------- kernel 4: state update (R8 4-lane layout) ---------------
__global__ __launch_bounds__(256) void k_state(
    const float* __restrict__ X, const float* __restrict__ Hprev,
    const float* __restrict__ Dv, float* __restrict__ Yout,
    float* __restrict__ Hout) {
    int tid  = blockIdx.x * 256 + threadIdx.x;
    int pair = tid >> 2;          // (b,d)
    int q    = tid & 3;           // state quarter
    int b    = pair >> 11;
    int d    = pair & 2047;

    float delta = g_delta[pair];
    float pole  = g_pole[pair];
    float xv    = X[pair];

    float4 hp = ((const float4*)Hprev)[(size_t)pair * 4 + q];
    float4 ab = ((const float4*)g_Abase)[d * 4 + q];
    float4 bt = ((const float4*)g_Bt)[b * 4 + q];
    float4 ct = ((const float4*)g_Ct)[b * 4 + q];

    float dbx = delta * xv;
    float4 h;
    h.x = __expf(delta * (ab.x + pole)) * hp.x + dbx * bt.x;
    h.y = __expf(delta * (ab.y + pole)) * hp.y + dbx * bt.y;
    h.z = __expf(delta * (ab.z + pole)) * hp.z + dbx * bt.z;
    h.w = __expf(delta * (ab.w + pole)) * hp.w + dbx * bt.w;

    ((float4*)Hout)[(size_t)pair * 4 + q] = h;

    float partial = h.x * ct.x + h.y * ct.y + h.z * ct.z + h.w * ct.w;
    partial += __shfl_xor_sync(0xffffffff, partial, 1);
    partial += __shfl_xor_sync(0xffffffff, partial, 2);
    if (q == 0) Yout[pair] = partial + Dv[d] * xv;
}

// ---------------- launch (serial, single stream) ----------------
extern "C" void kernel_launch(void* const* d_in, const int* in_sizes, int n_in,
                              void* d_out, int out_size) {
    const float* x      = (const float*)d_in[0];
    const float* h_prev = (const float*)d_in[1];
    const float* ev     = (const float*)d_in[2];
    const float* A_log  = (const float*)d_in[3];
    const float* Dv     = (const float*)d_in[4];
    const float* Wd     = (const float*)d_in[5];
    const float* bd     = (const float*)d_in[6];
    const float* We     = (const float*)d_in[7];
    const float* B_W1   = (const float*)d_in[8];
    const float* B_b1   = (const float*)d_in[9];
    const float* B_W2   = (const float*)d_in[10];
    const float* B_b2   = (const float*)d_in[11];
    const float* B_We   = (const float*)d_in[12];
    const float* A_We   = (const float*)d_in[13];
    const float* C_W    = (const float*)d_in[14];

    float* y_out = (float*)d_out;
    float* h_out = y_out + (size_t)BATCH * DMODEL;

    const int gemm_smem = 4 * STG * (int)sizeof(float);  // 73728 B
    cudaFuncSetAttribute(k_gemm_delta,
                         cudaFuncAttributeMaxDynamicSharedMemorySize, gemm_smem);

    k_pole<<<dim3(BATCH / 32, DMODEL / 128), 256>>>(ev, A_We, A_log);
    k_small_p<<<dim3(BATCH / 32, 4), 256>>>(x, B_W1, C_W);
    k_small_f<<<BATCH / 32, 256>>>(ev, B_b1, B_W2, B_b2, B_We);
    k_gemm_delta<<<dim3(DMODEL / 128, BATCH / 128), 256, gemm_smem>>>(
        x, Wd, ev, We, bd);
    k_state<<<(BATCH * DMODEL * 4) / 256, 256>>>(x, h_prev, Dv, y_out, h_out);
}

// round 12
// speedup vs baseline: 1.0923x; 1.0189x over previous
#include <cuda_runtime.h>
#include <cstdint>

#define BATCH   2048
#define DMODEL  2048
#define DSTATE  16
#define DEVENT  32

// ---------------- scratch ----------------
__device__ float g_delta[BATCH * DMODEL];   // delta_safe
__device__ float g_pole [BATCH * DMODEL];   // event @ A_We.T
__device__ float g_Abase[DMODEL * DSTATE];  // -exp(clip(A_log,-3,1))
__device__ float g_Bt   [BATCH * DSTATE];
__device__ float g_Ct   [BATCH * DSTATE];
__device__ float g_partH[4][BATCH * 2 * DSTATE];  // split-K partials of x@B_W1.T
__device__ float g_partC[4][BATCH * DSTATE];      // split-K partials of x@C_W.T

// ---------------- helpers ----------------
__device__ __forceinline__ void mma_tf32(float* c, const uint32_t* a, const uint32_t* b) {
    asm volatile(
        "mma.sync.aligned.m16n8k8.row.col.f32.tf32.tf32.f32 "
        "{%0,%1,%2,%3},{%4,%5,%6,%7},{%8,%9},{%0,%1,%2,%3};"
        : "+f"(c[0]), "+f"(c[1]), "+f"(c[2]), "+f"(c[3])
        : "r"(a[0]), "r"(a[1]), "r"(a[2]), "r"(a[3]), "r"(b[0]), "r"(b[1]));
}

__device__ __forceinline__ void ldsm4(uint32_t* r, uint32_t addr) {
    asm volatile(
        "ldmatrix.sync.aligned.m8n8.x4.shared.b16 {%0,%1,%2,%3}, [%4];"
        : "=r"(r[0]), "=r"(r[1]), "=r"(r[2]), "=r"(r[3]) : "r"(addr));
}

__device__ __forceinline__ void cp16(float* dst, const float* src) {
    uint32_t d = (uint32_t)__cvta_generic_to_shared(dst);
    asm volatile("cp.async.cg.shared.global [%0],[%1],16;\n" :: "r"(d), "l"(src));
}
__device__ __forceinline__ void cp_commit() {
    asm volatile("cp.async.commit_group;\n");
}

// ---------------- kernel 1: pole = event @ A_We.T (+ A_base fold) ---------
__global__ __launch_bounds__(256) void k_pole(const float* __restrict__ Ev,
                                              const float* __restrict__ A_We,
                                              const float* __restrict__ A_log) {
    __shared__ float Es[32][33];
    __shared__ float Ws[128][33];
    int t  = threadIdx.x;
    int b0 = blockIdx.x * 32;
    int d0 = blockIdx.y * 128;

    if (blockIdx.y == 0) {
        int i = (blockIdx.x * 256 + t) * 2;
#pragma unroll
        for (int e = 0; e < 2; ++e) {
            float a = A_log[i + e];
            a = fminf(fmaxf(a, -3.0f), 1.0f);
            g_Abase[i + e] = -__expf(a);
        }
    }

    {
        int idx = t;
        int r = idx >> 3, c4 = idx & 7;
        float4 v = *(const float4*)(Ev + (size_t)(b0 + r) * DEVENT + c4 * 4);
        Es[r][c4 * 4 + 0] = v.x; Es[r][c4 * 4 + 1] = v.y;
        Es[r][c4 * 4 + 2] = v.z; Es[r][c4 * 4 + 3] = v.w;
    }
#pragma unroll
    for (int i = 0; i < 4; ++i) {
        int idx = t + i * 256;
        int r = idx >> 3, c4 = idx & 7;
        float4 v = *(const float4*)(A_We + (size_t)(d0 + r) * DEVENT + c4 * 4);
        Ws[r][c4 * 4 + 0] = v.x; Ws[r][c4 * 4 + 1] = v.y;
        Ws[r][c4 * 4 + 2] = v.z; Ws[r][c4 * 4 + 3] = v.w;
    }
    __syncthreads();

    int d_sub = t & 127;
    int half  = t >> 7;
    for (int bs = half; bs < 32; bs += 2) {
        float acc = 0.0f;
#pragma unroll
        for (int e = 0; e < 32; ++e) acc += Es[bs][e] * Ws[d_sub][e];
        g_pole[(size_t)(b0 + bs) * DMODEL + d0 + d_sub] = acc;
    }
}

// ---------------- kernel 2a: split-K partials of x@B_W1.T and x@C_W.T -----
__global__ __launch_bounds__(256) void k_small_p(
    const float* __restrict__ X,
    const float* __restrict__ B_W1, const float* __restrict__ C_W) {
    __shared__ float Xs[32][132];
    __shared__ float Ws[48][132];

    int t    = threadIdx.x;
    int b0   = blockIdx.x * 32;
    int kb   = blockIdx.y * 512;
    int row  = t >> 3;
    int tcol = t & 7;

    float accH[4] = {0, 0, 0, 0};
    float accC[2] = {0, 0};

    for (int kc = kb; kc < kb + 512; kc += 128) {
#pragma unroll
        for (int i = 0; i < 4; ++i) {
            int idx = t + i * 256;
            int r = idx >> 5, c4 = idx & 31;
            float4 v = *(const float4*)(X + (size_t)(b0 + r) * DMODEL + kc + c4 * 4);
            *(float4*)(&Xs[r][c4 * 4]) = v;
        }
#pragma unroll
        for (int i = 0; i < 6; ++i) {
            int idx = t + i * 256;
            int r = idx >> 5, c4 = idx & 31;
            const float* src = (r < 32)
                ? (B_W1 + (size_t)r * DMODEL + kc + c4 * 4)
                : (C_W + (size_t)(r - 32) * DMODEL + kc + c4 * 4);
            float4 v = *(const float4*)src;
            *(float4*)(&Ws[r][c4 * 4]) = v;
        }
        __syncthreads();
#pragma unroll 4
        for (int kk = 0; kk < 128; ++kk) {
            float xv = Xs[row][kk];
#pragma unroll
            for (int i = 0; i < 4; ++i) accH[i] += xv * Ws[tcol + 8 * i][kk];
#pragma unroll
            for (int i = 0; i < 2; ++i) accC[i] += xv * Ws[32 + tcol + 8 * i][kk];
        }
        __syncthreads();
    }

    int ks = blockIdx.y;
#pragma unroll
    for (int i = 0; i < 4; ++i)
        g_partH[ks][(size_t)(b0 + row) * 32 + tcol + 8 * i] = accH[i];
#pragma unroll
    for (int i = 0; i < 2; ++i)
        g_partC[ks][(size_t)(b0 + row) * DSTATE + tcol + 8 * i] = accC[i];
}

// ---------------- kernel 2b: combine partials, silu, B_t / C_t ------------
__global__ __launch_bounds__(256) void k_small_f(
    const float* __restrict__ Ev,
    const float* __restrict__ B_b1, const float* __restrict__ B_W2,
    const float* __restrict__ B_b2, const float* __restrict__ B_We) {
    __shared__ float Hs[32][33];

    int t    = threadIdx.x;
    int b0   = blockIdx.x * 32;
    int row  = t >> 3;
    int tcol = t & 7;

#pragma unroll
    for (int i = 0; i < 4; ++i) {
        int j = tcol + 8 * i;
        size_t off = (size_t)(b0 + row) * 32 + j;
        float z = g_partH[0][off] + g_partH[1][off]
                + g_partH[2][off] + g_partH[3][off] + B_b1[j];
        Hs[row][j] = z / (1.0f + __expf(-z));
    }
#pragma unroll
    for (int i = 0; i < 2; ++i) {
        int n = tcol + 8 * i;
        size_t off = (size_t)(b0 + row) * DSTATE + n;
        g_Ct[off] = g_partC[0][off] + g_partC[1][off]
                  + g_partC[2][off] + g_partC[3][off];
    }
    __syncthreads();

    for (int o = t; o < 32 * 16; o += 256) {
        int r = o >> 4, n = o & 15;
        float acc = B_b2[n];
#pragma unroll
        for (int j = 0; j < 32; ++j) acc += Hs[r][j] * B_W2[n * 32 + j];
#pragma unroll
        for (int e = 0; e < 32; ++e) acc += Ev[(size_t)(b0 + r) * DEVENT + e] * B_We[n * 32 + e];
        g_Bt[(size_t)(b0 + r) * DSTATE + n] = acc;
    }
}

// ---------------- kernel 3: delta GEMM, cp.async + ldmatrix, 1 sync/tile --
#define STG 4608  // 128*36 floats per operand per stage

__global__ __launch_bounds__(256) void k_gemm_delta(
    const float* __restrict__ X, const float* __restrict__ Wd,
    const float* __restrict__ Ev, const float* __restrict__ We,
    const float* __restrict__ bd) {
    extern __shared__ float smbuf[];
    float* As = smbuf;            // [2][128][36]
    float* Bs = smbuf + 2 * STG;  // [2][128][36]

    const int tid  = threadIdx.x;
    const int row0 = blockIdx.y * 128;   // batch
    const int col0 = blockIdx.x * 128;   // d_model
    const int wid  = tid >> 5, lane = tid & 31;
    const int g    = lane >> 2, tg = lane & 3;
    const int wm0  = (wid & 1) * 64;
    const int wn0  = (wid >> 1) * 32;

    const uint32_t sAbase = (uint32_t)__cvta_generic_to_shared(As);
    const uint32_t sBbase = (uint32_t)__cvta_generic_to_shared(Bs);

    const int aRow = wm0 + ((lane >> 3) & 1) * 8 + (lane & 7);
    const int aCol = (lane >> 4) * 4;
    const int bRow = wn0 + (lane >> 4) * 8 + (lane & 7);
    const int bCol = ((lane >> 3) & 1) * 4;

    float acc[4][4][4];
#pragma unroll
    for (int mi = 0; mi < 4; ++mi)
#pragma unroll
        for (int ni = 0; ni < 4; ++ni)
#pragma unroll
            for (int r = 0; r < 4; ++r) acc[mi][ni][r] = 0.0f;

    auto load_tile = [&](int kt, int s) {
        const float *srcA, *srcB;
        int lda, ldb;
        if (kt < 64) {
            srcA = X  + (size_t)row0 * DMODEL + kt * 32; lda = DMODEL;
            srcB = Wd + (size_t)col0 * DMODEL + kt * 32; ldb = DMODEL;
        } else {
            srcA = Ev + (size_t)row0 * DEVENT; lda = DEVENT;
            srcB = We + (size_t)col0 * DEVENT; ldb = DEVENT;
        }
        float* as = As + s * STG;
        float* bs = Bs + s * STG;
#pragma unroll
        for (int i = 0; i < 4; ++i) {
            int idx = tid + i * 256;     // 1024 16B chunks per operand
            int m = idx >> 3, k4 = idx & 7;
            cp16(as + m * 36 + k4 * 4, srcA + (size_t)m * lda + k4 * 4);
            cp16(bs + m * 36 + k4 * 4, srcB + (size_t)m * ldb + k4 * 4);
        }
        cp_commit();
    };

    load_tile(0, 0);

    for (int kt = 0; kt < 65; ++kt) {
        // tile kt is the only outstanding group here
        asm volatile("cp.async.wait_group 0;\n");
        // single barrier: data visible to all AND stage (kt+1)&1 fully read
        __syncthreads();
        // prefetch next tile into the stage just freed (overlaps compute)
        if (kt < 64) load_tile(kt + 1, (kt + 1) & 1);

        const uint32_t sa = sAbase + (kt & 1) * STG * 4;
        const uint32_t sb = sBbase + (kt & 1) * STG * 4;
#pragma unroll
        for (int ks = 0; ks < 4; ++ks) {
            uint32_t a[4][4], b[4][2];
#pragma unroll
            for (int mi = 0; mi < 4; ++mi)
                ldsm4(a[mi], sa + (uint32_t)(((aRow + mi * 16) * 36
                                             + aCol + ks * 8) * 4));
#pragma unroll
            for (int np = 0; np < 2; ++np) {
                uint32_t r4[4];
                ldsm4(r4, sb + (uint32_t)(((bRow + np * 16) * 36
                                          + bCol + ks * 8) * 4));
                b[np * 2 + 0][0] = r4[0]; b[np * 2 + 0][1] = r4[1];
                b[np * 2 + 1][0] = r4[2]; b[np * 2 + 1][1] = r4[3];
            }
#pragma unroll
            for (int mi = 0; mi < 4; ++mi)
#pragma unroll
                for (int ni = 0; ni < 4; ++ni)
                    mma_tf32(acc[mi][ni], a[mi], b[ni]);
        }
    }

    // epilogue: delta_safe = min(softplus(z + bd), 2)
#pragma unroll
    for (int mi = 0; mi < 4; ++mi) {
        int rbase = row0 + wm0 + mi * 16 + g;
#pragma unroll
        for (int ni = 0; ni < 4; ++ni) {
            int cbase = col0 + wn0 + ni * 8 + tg * 2;
#pragma unroll
            for (int r = 0; r < 4; ++r) {
                int bb = rbase + (r >> 1) * 8;
                int dd = cbase + (r & 1);
                float z = acc[mi][ni][r] + __ldg(&bd[dd]);
                float sp = fmaxf(z, 0.0f) + __logf(1.0f + __expf(-fabsf(z)));
                g_delta[(size_t)bb * DMODEL + dd] = fminf(sp, 2.0f);
            }
        }
    }
}

// ---------------- kernel 4: state update, streaming-hinted ----------------
__global__ __launch_bounds__(256) void k_state(
    const float* __restrict__ X, const float* __restrict__ Hprev,
    const float* __restrict__ Dv, float* __restrict__ Yout,
    float* __restrict__ Hout) {
    int tid  = blockIdx.x * 256 + threadIdx.x;
    int pair = tid >> 2;          // (b,d)
    int q    = tid & 3;           // state quarter
    int b    = pair >> 11;
    int d    = pair & 2047;

    // read-once streams: evict-first so reused arrays keep L2
    float delta = __ldcs(g_delta + pair);
    float pole  = __ldcs(g_pole + pair);
    float xv    = __ldcs(X + pair);

    float4 hp = __ldcs((const float4*)Hprev + (size_t)pair * 4 + q);
    // reused arrays: normal caching path
    float4 ab = __ldg((const float4*)g_Abase + d * 4 + q);
    float4 bt = __ldg((const float4*)g_Bt + b * 4 + q);
    float4 ct = __ldg((const float4*)g_Ct + b * 4 + q);

    float dbx = delta * xv;
    float4 h;
    h.x = __expf(delta * (ab.x + pole)) * hp.x + dbx * bt.x;
    h.y = __expf(delta * (ab.y + pole)) * hp.y + dbx * bt.y;
    h.z = __expf(delta * (ab.z + pole)) * hp.z + dbx * bt.z;
    h.w = __expf(delta * (ab.w + pole)) * hp.w + dbx * bt.w;

    __stcs((float4*)Hout + (size_t)pair * 4 + q, h);

    float partial = h.x * ct.x + h.y * ct.y + h.z * ct.z + h.w * ct.w;
    partial += __shfl_xor_sync(0xffffffff, partial, 1);
    partial += __shfl_xor_sync(0xffffffff, partial, 2);
    if (q == 0) __stcs(Yout + pair, partial + __ldg(Dv + d) * xv);
}

// ---------------- launch (serial, single stream) ----------------
extern "C" void kernel_launch(void* const* d_in, const int* in_sizes, int n_in,
                              void* d_out, int out_size) {
    const float* x      = (const float*)d_in[0];
    const float* h_prev = (const float*)d_in[1];
    const float* ev     = (const float*)d_in[2];
    const float* A_log  = (const float*)d_in[3];
    const float* Dv     = (const float*)d_in[4];
    const float* Wd     = (const float*)d_in[5];
    const float* bd     = (const float*)d_in[6];
    const float* We     = (const float*)d_in[7];
    const float* B_W1   = (const float*)d_in[8];
    const float* B_b1   = (const float*)d_in[9];
    const float* B_W2   = (const float*)d_in[10];
    const float* B_b2   = (const float*)d_in[11];
    const float* B_We   = (const float*)d_in[12];
    const float* A_We   = (const float*)d_in[13];
    const float* C_W    = (const float*)d_in[14];

    float* y_out = (float*)d_out;
    float* h_out = y_out + (size_t)BATCH * DMODEL;

    const int gemm_smem = 4 * STG * (int)sizeof(float);  // 73728 B
    cudaFuncSetAttribute(k_gemm_delta,
                         cudaFuncAttributeMaxDynamicSharedMemorySize, gemm_smem);

    k_pole<<<dim3(BATCH / 32, DMODEL / 128), 256>>>(ev, A_We, A_log);
    k_small_p<<<dim3(BATCH / 32, 4), 256>>>(x, B_W1, C_W);
    k_small_f<<<BATCH / 32, 256>>>(ev, B_b1, B_W2, B_b2, B_We);
    k_gemm_delta<<<dim3(DMODEL / 128, BATCH / 128), 256, gemm_smem>>>(
        x, Wd, ev, We, bd);
    k_state<<<(BATCH * DMODEL * 4) / 256, 256>>>(x, h_prev, Dv, y_out, h_out);
}

// round 14
// speedup vs baseline: 1.2998x; 1.1900x over previous
#include <cuda_runtime.h>
#include <cuda_bf16.h>
#include <cstdint>

#define BATCH   2048
#define DMODEL  2048
#define DSTATE  16
#define DEVENT  32

// ---------------- scratch ----------------
__device__ float g_delta[BATCH * DMODEL];   // delta_safe
__device__ float g_pole [BATCH * DMODEL];   // event @ A_We.T
__device__ float g_Abase[DMODEL * DSTATE];  // -exp(clip(A_log,-3,1))
__device__ float g_Bt   [BATCH * DSTATE];
__device__ float g_Ct   [BATCH * DSTATE];
__device__ float g_partH[4][BATCH * 2 * DSTATE];  // split-K partials of x@B_W1.T
__device__ float g_partC[4][BATCH * DSTATE];      // split-K partials of x@C_W.T
__device__ __nv_bfloat16 g_Xh [BATCH * DMODEL];   // bf16 copies for delta GEMM
__device__ __nv_bfloat16 g_Wdh[DMODEL * DMODEL];
__device__ __nv_bfloat16 g_Evh[BATCH * DEVENT];
__device__ __nv_bfloat16 g_Weh[DMODEL * DEVENT];

// ---------------- helpers ----------------
__device__ __forceinline__ void mma_bf16(float* c, const uint32_t* a, const uint32_t* b) {
    asm volatile(
        "mma.sync.aligned.m16n8k16.row.col.f32.bf16.bf16.f32 "
        "{%0,%1,%2,%3},{%4,%5,%6,%7},{%8,%9},{%0,%1,%2,%3};"
        : "+f"(c[0]), "+f"(c[1]), "+f"(c[2]), "+f"(c[3])
        : "r"(a[0]), "r"(a[1]), "r"(a[2]), "r"(a[3]), "r"(b[0]), "r"(b[1]));
}

__device__ __forceinline__ void ldsm4(uint32_t* r, uint32_t addr) {
    asm volatile(
        "ldmatrix.sync.aligned.m8n8.x4.shared.b16 {%0,%1,%2,%3}, [%4];"
        : "=r"(r[0]), "=r"(r[1]), "=r"(r[2]), "=r"(r[3]) : "r"(addr));
}

__device__ __forceinline__ void cp16(void* dst, const void* src) {
    uint32_t d = (uint32_t)__cvta_generic_to_shared(dst);
    asm volatile("cp.async.cg.shared.global [%0],[%1],16;\n" :: "r"(d), "l"(src));
}
__device__ __forceinline__ void cp_commit() {
    asm volatile("cp.async.commit_group;\n");
}

// ---------------- kernel 0: fp32 -> bf16 copies ----------------
__global__ __launch_bounds__(256) void k_prep(
    const float* __restrict__ X, const float* __restrict__ Wd,
    const float* __restrict__ Ev, const float* __restrict__ We) {
    int i4 = (blockIdx.x * 256 + threadIdx.x) * 4;   // grid covers 4M elements
    if (i4 < BATCH * DMODEL) {
        float4 vx = *(const float4*)(X + i4);
        float4 vw = *(const float4*)(Wd + i4);
        __nv_bfloat162* xo = (__nv_bfloat162*)(g_Xh + i4);
        __nv_bfloat162* wo = (__nv_bfloat162*)(g_Wdh + i4);
        xo[0] = __floats2bfloat162_rn(vx.x, vx.y);
        xo[1] = __floats2bfloat162_rn(vx.z, vx.w);
        wo[0] = __floats2bfloat162_rn(vw.x, vw.y);
        wo[1] = __floats2bfloat162_rn(vw.z, vw.w);
    }
    if (i4 < BATCH * DEVENT) {
        float4 ve = *(const float4*)(Ev + i4);
        float4 vq = *(const float4*)(We + i4);
        __nv_bfloat162* eo = (__nv_bfloat162*)(g_Evh + i4);
        __nv_bfloat162* qo = (__nv_bfloat162*)(g_Weh + i4);
        eo[0] = __floats2bfloat162_rn(ve.x, ve.y);
        eo[1] = __floats2bfloat162_rn(ve.z, ve.w);
        qo[0] = __floats2bfloat162_rn(vq.x, vq.y);
        qo[1] = __floats2bfloat162_rn(vq.z, vq.w);
    }
}

// ---------------- kernel 1: pole = event @ A_We.T (+ A_base fold) ---------
__global__ __launch_bounds__(256) void k_pole(const float* __restrict__ Ev,
                                              const float* __restrict__ A_We,
                                              const float* __restrict__ A_log) {
    __shared__ float Es[32][33];
    __shared__ float Ws[128][33];
    int t  = threadIdx.x;
    int b0 = blockIdx.x * 32;
    int d0 = blockIdx.y * 128;

    if (blockIdx.y == 0) {
        int i = (blockIdx.x * 256 + t) * 2;
#pragma unroll
        for (int e = 0; e < 2; ++e) {
            float a = A_log[i + e];
            a = fminf(fmaxf(a, -3.0f), 1.0f);
            g_Abase[i + e] = -__expf(a);
        }
    }

    {
        int idx = t;
        int r = idx >> 3, c4 = idx & 7;
        float4 v = *(const float4*)(Ev + (size_t)(b0 + r) * DEVENT + c4 * 4);
        Es[r][c4 * 4 + 0] = v.x; Es[r][c4 * 4 + 1] = v.y;
        Es[r][c4 * 4 + 2] = v.z; Es[r][c4 * 4 + 3] = v.w;
    }
#pragma unroll
    for (int i = 0; i < 4; ++i) {
        int idx = t + i * 256;
        int r = idx >> 3, c4 = idx & 7;
        float4 v = *(const float4*)(A_We + (size_t)(d0 + r) * DEVENT + c4 * 4);
        Ws[r][c4 * 4 + 0] = v.x; Ws[r][c4 * 4 + 1] = v.y;
        Ws[r][c4 * 4 + 2] = v.z; Ws[r][c4 * 4 + 3] = v.w;
    }
    __syncthreads();

    int d_sub = t & 127;
    int half  = t >> 7;
    for (int bs = half; bs < 32; bs += 2) {
        float acc = 0.0f;
#pragma unroll
        for (int e = 0; e < 32; ++e) acc += Es[bs][e] * Ws[d_sub][e];
        g_pole[(size_t)(b0 + bs) * DMODEL + d0 + d_sub] = acc;
    }
}

// ---------------- kernel 2a: split-K partials of x@B_W1.T and x@C_W.T -----
__global__ __launch_bounds__(256) void k_small_p(
    const float* __restrict__ X,
    const float* __restrict__ B_W1, const float* __restrict__ C_W) {
    __shared__ float Xs[32][132];
    __shared__ float Ws[48][132];

    int t    = threadIdx.x;
    int b0   = blockIdx.x * 32;
    int kb   = blockIdx.y * 512;
    int row  = t >> 3;
    int tcol = t & 7;

    float accH[4] = {0, 0, 0, 0};
    float accC[2] = {0, 0};

    for (int kc = kb; kc < kb + 512; kc += 128) {
#pragma unroll
        for (int i = 0; i < 4; ++i) {
            int idx = t + i * 256;
            int r = idx >> 5, c4 = idx & 31;
            float4 v = *(const float4*)(X + (size_t)(b0 + r) * DMODEL + kc + c4 * 4);
            *(float4*)(&Xs[r][c4 * 4]) = v;
        }
#pragma unroll
        for (int i = 0; i < 6; ++i) {
            int idx = t + i * 256;
            int r = idx >> 5, c4 = idx & 31;
            const float* src = (r < 32)
                ? (B_W1 + (size_t)r * DMODEL + kc + c4 * 4)
                : (C_W + (size_t)(r - 32) * DMODEL + kc + c4 * 4);
            float4 v = *(const float4*)src;
            *(float4*)(&Ws[r][c4 * 4]) = v;
        }
        __syncthreads();
#pragma unroll 4
        for (int kk = 0; kk < 128; ++kk) {
            float xv = Xs[row][kk];
#pragma unroll
            for (int i = 0; i < 4; ++i) accH[i] += xv * Ws[tcol + 8 * i][kk];
#pragma unroll
            for (int i = 0; i < 2; ++i) accC[i] += xv * Ws[32 + tcol + 8 * i][kk];
        }
        __syncthreads();
    }

    int ks = blockIdx.y;
#pragma unroll
    for (int i = 0; i < 4; ++i)
        g_partH[ks][(size_t)(b0 + row) * 32 + tcol + 8 * i] = accH[i];
#pragma unroll
    for (int i = 0; i < 2; ++i)
        g_partC[ks][(size_t)(b0 + row) * DSTATE + tcol + 8 * i] = accC[i];
}

// ---------------- kernel 2b: combine partials, silu, B_t / C_t ------------
__global__ __launch_bounds__(256) void k_small_f(
    const float* __restrict__ Ev,
    const float* __restrict__ B_b1, const float* __restrict__ B_W2,
    const float* __restrict__ B_b2, const float* __restrict__ B_We) {
    __shared__ float Hs[32][33];

    int t    = threadIdx.x;
    int b0   = blockIdx.x * 32;
    int row  = t >> 3;
    int tcol = t & 7;

#pragma unroll
    for (int i = 0; i < 4; ++i) {
        int j = tcol + 8 * i;
        size_t off = (size_t)(b0 + row) * 32 + j;
        float z = g_partH[0][off] + g_partH[1][off]
                + g_partH[2][off] + g_partH[3][off] + B_b1[j];
        Hs[row][j] = z / (1.0f + __expf(-z));
    }
#pragma unroll
    for (int i = 0; i < 2; ++i) {
        int n = tcol + 8 * i;
        size_t off = (size_t)(b0 + row) * DSTATE + n;
        g_Ct[off] = g_partC[0][off] + g_partC[1][off]
                  + g_partC[2][off] + g_partC[3][off];
    }
    __syncthreads();

    for (int o = t; o < 32 * 16; o += 256) {
        int r = o >> 4, n = o & 15;
        float acc = B_b2[n];
#pragma unroll
        for (int j = 0; j < 32; ++j) acc += Hs[r][j] * B_W2[n * 32 + j];
#pragma unroll
        for (int e = 0; e < 32; ++e) acc += Ev[(size_t)(b0 + r) * DEVENT + e] * B_We[n * 32 + e];
        g_Bt[(size_t)(b0 + r) * DSTATE + n] = acc;
    }
}

// ---------------- kernel 3: delta GEMM in bf16 (m16n8k16) -----------------
// stage: 128 rows x 40 bf16 (80 B row stride, conflict-free for ldmatrix)
#define STGB 10240   // bytes per operand stage

__global__ __launch_bounds__(256) void k_gemm_delta(const float* __restrict__ bd) {
    __shared__ char smem[4 * STGB];   // [2 stages][A], [2 stages][B]

    const int tid  = threadIdx.x;
    const int row0 = blockIdx.y * 128;   // batch
    const int col0 = blockIdx.x * 128;   // d_model
    const int wid  = tid >> 5, lane = tid & 31;
    const int g    = lane >> 2, tg = lane & 3;
    const int wm0  = (wid & 1) * 64;
    const int wn0  = (wid >> 1) * 32;

    const uint32_t sAbase = (uint32_t)__cvta_generic_to_shared(smem);
    const uint32_t sBbase = sAbase + 2 * STGB;

    // ldmatrix lane addressing
    const int aRow  = wm0 + ((lane >> 3) & 1) * 8 + (lane & 7);
    const int aColB = (lane >> 4) * 16;           // k0 / k8 halves (bytes)
    const int bRow  = wn0 + (lane >> 4) * 8 + (lane & 7);
    const int bColB = ((lane >> 3) & 1) * 16;

    float acc[4][4][4];
#pragma unroll
    for (int mi = 0; mi < 4; ++mi)
#pragma unroll
        for (int ni = 0; ni < 4; ++ni)
#pragma unroll
            for (int r = 0; r < 4; ++r) acc[mi][ni][r] = 0.0f;

    auto load_tile = [&](int kt, int s) {
        const __nv_bfloat16 *srcA, *srcB;
        int lda, ldb;
        if (kt < 64) {
            srcA = g_Xh  + (size_t)row0 * DMODEL + kt * 32; lda = DMODEL;
            srcB = g_Wdh + (size_t)col0 * DMODEL + kt * 32; ldb = DMODEL;
        } else {
            srcA = g_Evh + (size_t)row0 * DEVENT; lda = DEVENT;
            srcB = g_Weh + (size_t)col0 * DEVENT; ldb = DEVENT;
        }
        char* as = smem + s * STGB;
        char* bs = smem + 2 * STGB + s * STGB;
#pragma unroll
        for (int i = 0; i < 2; ++i) {
            int idx = tid + i * 256;     // 512 16B chunks per operand
            int m = idx >> 2, c = idx & 3;
            cp16(as + m * 80 + c * 16, srcA + (size_t)m * lda + c * 8);
            cp16(bs + m * 80 + c * 16, srcB + (size_t)m * ldb + c * 8);
        }
        cp_commit();
    };

    load_tile(0, 0);

    for (int kt = 0; kt < 65; ++kt) {
        asm volatile("cp.async.wait_group 0;\n");
        __syncthreads();
        if (kt < 64) load_tile(kt + 1, (kt + 1) & 1);

        const uint32_t sa = sAbase + (kt & 1) * STGB;
        const uint32_t sb = sBbase + (kt & 1) * STGB;
#pragma unroll
        for (int ks = 0; ks < 2; ++ks) {   // two K=16 steps per 32-wide tile
            uint32_t a[4][4], b[4][2];
#pragma unroll
            for (int mi = 0; mi < 4; ++mi)
                ldsm4(a[mi], sa + (uint32_t)((aRow + mi * 16) * 80
                                             + ks * 32 + aColB));
#pragma unroll
            for (int np = 0; np < 2; ++np) {
                uint32_t r4[4];
                ldsm4(r4, sb + (uint32_t)((bRow + np * 16) * 80
                                          + ks * 32 + bColB));
                b[np * 2 + 0][0] = r4[0]; b[np * 2 + 0][1] = r4[1];
                b[np * 2 + 1][0] = r4[2]; b[np * 2 + 1][1] = r4[3];
            }
#pragma unroll
            for (int mi = 0; mi < 4; ++mi)
#pragma unroll
                for (int ni = 0; ni < 4; ++ni)
                    mma_bf16(acc[mi][ni], a[mi], b[ni]);
        }
    }

    // epilogue: delta_safe = min(softplus(z + bd), 2)
#pragma unroll
    for (int mi = 0; mi < 4; ++mi) {
        int rbase = row0 + wm0 + mi * 16 + g;
#pragma unroll
        for (int ni = 0; ni < 4; ++ni) {
            int cbase = col0 + wn0 + ni * 8 + tg * 2;
#pragma unroll
            for (int r = 0; r < 4; ++r) {
                int bb = rbase + (r >> 1) * 8;
                int dd = cbase + (r & 1);
                float z = acc[mi][ni][r] + __ldg(&bd[dd]);
                float sp = fmaxf(z, 0.0f) + __logf(1.0f + __expf(-fabsf(z)));
                g_delta[(size_t)bb * DMODEL + dd] = fminf(sp, 2.0f);
            }
        }
    }
}

// ---------------- kernel 4: state update, streaming-hinted ----------------
__global__ __launch_bounds__(256) void k_state(
    const float* __restrict__ X, const float* __restrict__ Hprev,
    const float* __restrict__ Dv, float* __restrict__ Yout,
    float* __restrict__ Hout) {
    int tid  = blockIdx.x * 256 + threadIdx.x;
    int pair = tid >> 2;          // (b,d)
    int q    = tid & 3;           // state quarter
    int b    = pair >> 11;
    int d    = pair & 2047;

    float delta = __ldcs(g_delta + pair);
    float pole  = __ldcs(g_pole + pair);
    float xv    = __ldcs(X + pair);

    float4 hp = __ldcs((const float4*)Hprev + (size_t)pair * 4 + q);
    float4 ab = __ldg((const float4*)g_Abase + d * 4 + q);
    float4 bt = __ldg((const float4*)g_Bt + b * 4 + q);
    float4 ct = __ldg((const float4*)g_Ct + b * 4 + q);

    float dbx = delta * xv;
    float4 h;
    h.x = __expf(delta * (ab.x + pole)) * hp.x + dbx * bt.x;
    h.y = __expf(delta * (ab.y + pole)) * hp.y + dbx * bt.y;
    h.z = __expf(delta * (ab.z + pole)) * hp.z + dbx * bt.z;
    h.w = __expf(delta * (ab.w + pole)) * hp.w + dbx * bt.w;

    __stcs((float4*)Hout + (size_t)pair * 4 + q, h);

    float partial = h.x * ct.x + h.y * ct.y + h.z * ct.z + h.w * ct.w;
    partial += __shfl_xor_sync(0xffffffff, partial, 1);
    partial += __shfl_xor_sync(0xffffffff, partial, 2);
    if (q == 0) __stcs(Yout + pair, partial + __ldg(Dv + d) * xv);
}

// ---------------- launch (serial, single stream) ----------------
extern "C" void kernel_launch(void* const* d_in, const int* in_sizes, int n_in,
                              void* d_out, int out_size) {
    const float* x      = (const float*)d_in[0];
    const float* h_prev = (const float*)d_in[1];
    const float* ev     = (const float*)d_in[2];
    const float* A_log  = (const float*)d_in[3];
    const float* Dv     = (const float*)d_in[4];
    const float* Wd     = (const float*)d_in[5];
    const float* bd     = (const float*)d_in[6];
    const float* We     = (const float*)d_in[7];
    const float* B_W1   = (const float*)d_in[8];
    const float* B_b1   = (const float*)d_in[9];
    const float* B_W2   = (const float*)d_in[10];
    const float* B_b2   = (const float*)d_in[11];
    const float* B_We   = (const float*)d_in[12];
    const float* A_We   = (const float*)d_in[13];
    const float* C_W    = (const float*)d_in[14];

    float* y_out = (float*)d_out;
    float* h_out = y_out + (size_t)BATCH * DMODEL;

    k_prep<<<(BATCH * DMODEL / 4 + 255) / 256, 256>>>(x, Wd, ev, We);
    k_pole<<<dim3(BATCH / 32, DMODEL / 128), 256>>>(ev, A_We, A_log);
    k_small_p<<<dim3(BATCH / 32, 4), 256>>>(x, B_W1, C_W);
    k_small_f<<<BATCH / 32, 256>>>(ev, B_b1, B_W2, B_b2, B_We);
    k_gemm_delta<<<dim3(DMODEL / 128, BATCH / 128), 256>>>(bd);
    k_state<<<(BATCH * DMODEL * 4) / 256, 256>>>(x, h_prev, Dv, y_out, h_out);
}

// round 15
// speedup vs baseline: 1.3204x; 1.0159x over previous
#include <cuda_runtime.h>
#include <cuda_bf16.h>
#include <cstdint>

#define BATCH   2048
#define DMODEL  2048
#define DSTATE  16
#define DEVENT  32

// ---------------- scratch ----------------
__device__ float g_delta[BATCH * DMODEL];   // delta_safe
__device__ float g_pole [BATCH * DMODEL];   // event @ A_We.T
__device__ float g_Abase[DMODEL * DSTATE];  // -exp(clip(A_log,-3,1))
__device__ float g_Bt   [BATCH * DSTATE];
__device__ float g_Ct   [BATCH * DSTATE];
__device__ float g_partH[4][BATCH * 2 * DSTATE];  // split-K partials of x@B_W1.T
__device__ float g_partC[4][BATCH * DSTATE];      // split-K partials of x@C_W.T
__device__ __nv_bfloat16 g_Xh [BATCH * DMODEL];   // bf16 copies for delta GEMM
__device__ __nv_bfloat16 g_Wdh[DMODEL * DMODEL];
__device__ __nv_bfloat16 g_Evh[BATCH * DEVENT];
__device__ __nv_bfloat16 g_Weh[DMODEL * DEVENT];

// ---------------- helpers ----------------
__device__ __forceinline__ void mma_bf16(float* c, const uint32_t* a, const uint32_t* b) {
    asm volatile(
        "mma.sync.aligned.m16n8k16.row.col.f32.bf16.bf16.f32 "
        "{%0,%1,%2,%3},{%4,%5,%6,%7},{%8,%9},{%0,%1,%2,%3};"
        : "+f"(c[0]), "+f"(c[1]), "+f"(c[2]), "+f"(c[3])
        : "r"(a[0]), "r"(a[1]), "r"(a[2]), "r"(a[3]), "r"(b[0]), "r"(b[1]));
}

__device__ __forceinline__ void ldsm4(uint32_t* r, uint32_t addr) {
    asm volatile(
        "ldmatrix.sync.aligned.m8n8.x4.shared.b16 {%0,%1,%2,%3}, [%4];"
        : "=r"(r[0]), "=r"(r[1]), "=r"(r[2]), "=r"(r[3]) : "r"(addr));
}

__device__ __forceinline__ void cp16(void* dst, const void* src) {
    uint32_t d = (uint32_t)__cvta_generic_to_shared(dst);
    asm volatile("cp.async.cg.shared.global [%0],[%1],16;\n" :: "r"(d), "l"(src));
}
__device__ __forceinline__ void cp_commit() {
    asm volatile("cp.async.commit_group;\n");
}

// ---------------- kernel 0: fp32 -> bf16 copies ----------------
__global__ __launch_bounds__(256) void k_prep(
    const float* __restrict__ X, const float* __restrict__ Wd,
    const float* __restrict__ Ev, const float* __restrict__ We) {
    int i4 = (blockIdx.x * 256 + threadIdx.x) * 4;   // grid covers 4M elements
    if (i4 < BATCH * DMODEL) {
        float4 vx = *(const float4*)(X + i4);
        float4 vw = *(const float4*)(Wd + i4);
        __nv_bfloat162* xo = (__nv_bfloat162*)(g_Xh + i4);
        __nv_bfloat162* wo = (__nv_bfloat162*)(g_Wdh + i4);
        xo[0] = __floats2bfloat162_rn(vx.x, vx.y);
        xo[1] = __floats2bfloat162_rn(vx.z, vx.w);
        wo[0] = __floats2bfloat162_rn(vw.x, vw.y);
        wo[1] = __floats2bfloat162_rn(vw.z, vw.w);
    }
    if (i4 < BATCH * DEVENT) {
        float4 ve = *(const float4*)(Ev + i4);
        float4 vq = *(const float4*)(We + i4);
        __nv_bfloat162* eo = (__nv_bfloat162*)(g_Evh + i4);
        __nv_bfloat162* qo = (__nv_bfloat162*)(g_Weh + i4);
        eo[0] = __floats2bfloat162_rn(ve.x, ve.y);
        eo[1] = __floats2bfloat162_rn(ve.z, ve.w);
        qo[0] = __floats2bfloat162_rn(vq.x, vq.y);
        qo[1] = __floats2bfloat162_rn(vq.z, vq.w);
    }
}

// ---------------- kernel 1: pole = event @ A_We.T (+ A_base fold) ---------
__global__ __launch_bounds__(256) void k_pole(const float* __restrict__ Ev,
                                              const float* __restrict__ A_We,
                                              const float* __restrict__ A_log) {
    __shared__ float Es[32][33];
    __shared__ float Ws[128][33];
    int t  = threadIdx.x;
    int b0 = blockIdx.x * 32;
    int d0 = blockIdx.y * 128;

    if (blockIdx.y == 0) {
        int i = (blockIdx.x * 256 + t) * 2;
#pragma unroll
        for (int e = 0; e < 2; ++e) {
            float a = A_log[i + e];
            a = fminf(fmaxf(a, -3.0f), 1.0f);
            g_Abase[i + e] = -__expf(a);
        }
    }

    {
        int idx = t;
        int r = idx >> 3, c4 = idx & 7;
        float4 v = *(const float4*)(Ev + (size_t)(b0 + r) * DEVENT + c4 * 4);
        Es[r][c4 * 4 + 0] = v.x; Es[r][c4 * 4 + 1] = v.y;
        Es[r][c4 * 4 + 2] = v.z; Es[r][c4 * 4 + 3] = v.w;
    }
#pragma unroll
    for (int i = 0; i < 4; ++i) {
        int idx = t + i * 256;
        int r = idx >> 3, c4 = idx & 7;
        float4 v = *(const float4*)(A_We + (size_t)(d0 + r) * DEVENT + c4 * 4);
        Ws[r][c4 * 4 + 0] = v.x; Ws[r][c4 * 4 + 1] = v.y;
        Ws[r][c4 * 4 + 2] = v.z; Ws[r][c4 * 4 + 3] = v.w;
    }
    __syncthreads();

    int d_sub = t & 127;
    int half  = t >> 7;
    for (int bs = half; bs < 32; bs += 2) {
        float acc = 0.0f;
#pragma unroll
        for (int e = 0; e < 32; ++e) acc += Es[bs][e] * Ws[d_sub][e];
        g_pole[(size_t)(b0 + bs) * DMODEL + d0 + d_sub] = acc;
    }
}

// ---------------- kernel 2a: split-K partials of x@B_W1.T and x@C_W.T -----
__global__ __launch_bounds__(256) void k_small_p(
    const float* __restrict__ X,
    const float* __restrict__ B_W1, const float* __restrict__ C_W) {
    __shared__ float Xs[32][132];
    __shared__ float Ws[48][132];

    int t    = threadIdx.x;
    int b0   = blockIdx.x * 32;
    int kb   = blockIdx.y * 512;
    int row  = t >> 3;
    int tcol = t & 7;

    float accH[4] = {0, 0, 0, 0};
    float accC[2] = {0, 0};

    for (int kc = kb; kc < kb + 512; kc += 128) {
#pragma unroll
        for (int i = 0; i < 4; ++i) {
            int idx = t + i * 256;
            int r = idx >> 5, c4 = idx & 31;
            float4 v = *(const float4*)(X + (size_t)(b0 + r) * DMODEL + kc + c4 * 4);
            *(float4*)(&Xs[r][c4 * 4]) = v;
        }
#pragma unroll
        for (int i = 0; i < 6; ++i) {
            int idx = t + i * 256;
            int r = idx >> 5, c4 = idx & 31;
            const float* src = (r < 32)
                ? (B_W1 + (size_t)r * DMODEL + kc + c4 * 4)
                : (C_W + (size_t)(r - 32) * DMODEL + kc + c4 * 4);
            float4 v = *(const float4*)src;
            *(float4*)(&Ws[r][c4 * 4]) = v;
        }
        __syncthreads();
#pragma unroll 4
        for (int kk = 0; kk < 128; ++kk) {
            float xv = Xs[row][kk];
#pragma unroll
            for (int i = 0; i < 4; ++i) accH[i] += xv * Ws[tcol + 8 * i][kk];
#pragma unroll
            for (int i = 0; i < 2; ++i) accC[i] += xv * Ws[32 + tcol + 8 * i][kk];
        }
        __syncthreads();
    }

    int ks = blockIdx.y;
#pragma unroll
    for (int i = 0; i < 4; ++i)
        g_partH[ks][(size_t)(b0 + row) * 32 + tcol + 8 * i] = accH[i];
#pragma unroll
    for (int i = 0; i < 2; ++i)
        g_partC[ks][(size_t)(b0 + row) * DSTATE + tcol + 8 * i] = accC[i];
}

// ---------------- kernel 2b: combine partials (256 blocks x 8 rows) -------
__global__ __launch_bounds__(256) void k_small_f(
    const float* __restrict__ Ev,
    const float* __restrict__ B_b1, const float* __restrict__ B_W2,
    const float* __restrict__ B_b2, const float* __restrict__ B_We) {
    __shared__ float Hs[8][33];

    int t   = threadIdx.x;
    int b0  = blockIdx.x * 8;
    int row = t >> 5, col = t & 31;   // 8 rows x 32 cols

    {
        size_t off = (size_t)(b0 + row) * 32 + col;
        float z = g_partH[0][off] + g_partH[1][off]
                + g_partH[2][off] + g_partH[3][off] + B_b1[col];
        Hs[row][col] = z / (1.0f + __expf(-z));
    }
    if (t < 128) {
        int r = t >> 4, n = t & 15;
        size_t off = (size_t)(b0 + r) * DSTATE + n;
        g_Ct[off] = g_partC[0][off] + g_partC[1][off]
                  + g_partC[2][off] + g_partC[3][off];
    }
    __syncthreads();

    if (t < 128) {
        int r = t >> 4, n = t & 15;
        float acc = B_b2[n];
#pragma unroll
        for (int j = 0; j < 32; ++j) acc += Hs[r][j] * B_W2[n * 32 + j];
#pragma unroll
        for (int e = 0; e < 32; ++e)
            acc += Ev[(size_t)(b0 + r) * DEVENT + e] * B_We[n * 32 + e];
        g_Bt[(size_t)(b0 + r) * DSTATE + n] = acc;
    }
}

// ---------------- kernel 3: delta GEMM in bf16 (m16n8k16), row-offset -----
#define STGB 10240   // bytes per operand stage

__global__ __launch_bounds__(256) void k_gemm_delta(const float* __restrict__ bd,
                                                    int rowoff) {
    __shared__ char smem[4 * STGB];   // [2 stages][A], [2 stages][B]

    const int tid  = threadIdx.x;
    const int row0 = rowoff + blockIdx.y * 128;   // batch
    const int col0 = blockIdx.x * 128;            // d_model
    const int wid  = tid >> 5, lane = tid & 31;
    const int g    = lane >> 2, tg = lane & 3;
    const int wm0  = (wid & 1) * 64;
    const int wn0  = (wid >> 1) * 32;

    const uint32_t sAbase = (uint32_t)__cvta_generic_to_shared(smem);
    const uint32_t sBbase = sAbase + 2 * STGB;

    const int aRow  = wm0 + ((lane >> 3) & 1) * 8 + (lane & 7);
    const int aColB = (lane >> 4) * 16;
    const int bRow  = wn0 + (lane >> 4) * 8 + (lane & 7);
    const int bColB = ((lane >> 3) & 1) * 16;

    float acc[4][4][4];
#pragma unroll
    for (int mi = 0; mi < 4; ++mi)
#pragma unroll
        for (int ni = 0; ni < 4; ++ni)
#pragma unroll
            for (int r = 0; r < 4; ++r) acc[mi][ni][r] = 0.0f;

    auto load_tile = [&](int kt, int s) {
        const __nv_bfloat16 *srcA, *srcB;
        int lda, ldb;
        if (kt < 64) {
            srcA = g_Xh  + (size_t)row0 * DMODEL + kt * 32; lda = DMODEL;
            srcB = g_Wdh + (size_t)col0 * DMODEL + kt * 32; ldb = DMODEL;
        } else {
            srcA = g_Evh + (size_t)row0 * DEVENT; lda = DEVENT;
            srcB = g_Weh + (size_t)col0 * DEVENT; ldb = DEVENT;
        }
        char* as = smem + s * STGB;
        char* bs = smem + 2 * STGB + s * STGB;
#pragma unroll
        for (int i = 0; i < 2; ++i) {
            int idx = tid + i * 256;     // 512 16B chunks per operand
            int m = idx >> 2, c = idx & 3;
            cp16(as + m * 80 + c * 16, srcA + (size_t)m * lda + c * 8);
            cp16(bs + m * 80 + c * 16, srcB + (size_t)m * ldb + c * 8);
        }
        cp_commit();
    };

    load_tile(0, 0);

    for (int kt = 0; kt < 65; ++kt) {
        asm volatile("cp.async.wait_group 0;\n");
        __syncthreads();
        if (kt < 64) load_tile(kt + 1, (kt + 1) & 1);

        const uint32_t sa = sAbase + (kt & 1) * STGB;
        const uint32_t sb = sBbase + (kt & 1) * STGB;
#pragma unroll
        for (int ks = 0; ks < 2; ++ks) {
            uint32_t a[4][4], b[4][2];
#pragma unroll
            for (int mi = 0; mi < 4; ++mi)
                ldsm4(a[mi], sa + (uint32_t)((aRow + mi * 16) * 80
                                             + ks * 32 + aColB));
#pragma unroll
            for (int np = 0; np < 2; ++np) {
                uint32_t r4[4];
                ldsm4(r4, sb + (uint32_t)((bRow + np * 16) * 80
                                          + ks * 32 + bColB));
                b[np * 2 + 0][0] = r4[0]; b[np * 2 + 0][1] = r4[1];
                b[np * 2 + 1][0] = r4[2]; b[np * 2 + 1][1] = r4[3];
            }
#pragma unroll
            for (int mi = 0; mi < 4; ++mi)
#pragma unroll
                for (int ni = 0; ni < 4; ++ni)
                    mma_bf16(acc[mi][ni], a[mi], b[ni]);
        }
    }

    // epilogue: delta_safe = min(softplus(z + bd), 2)
#pragma unroll
    for (int mi = 0; mi < 4; ++mi) {
        int rbase = row0 + wm0 + mi * 16 + g;
#pragma unroll
        for (int ni = 0; ni < 4; ++ni) {
            int cbase = col0 + wn0 + ni * 8 + tg * 2;
#pragma unroll
            for (int r = 0; r < 4; ++r) {
                int bb = rbase + (r >> 1) * 8;
                int dd = cbase + (r & 1);
                float z = acc[mi][ni][r] + __ldg(&bd[dd]);
                float sp = fmaxf(z, 0.0f) + __logf(1.0f + __expf(-fabsf(z)));
                g_delta[(size_t)bb * DMODEL + dd] = fminf(sp, 2.0f);
            }
        }
    }
}

// ---------------- kernel 4: state update, streaming-hinted, row-offset ----
__global__ __launch_bounds__(256) void k_state(
    const float* __restrict__ X, const float* __restrict__ Hprev,
    const float* __restrict__ Dv, float* __restrict__ Yout,
    float* __restrict__ Hout, int pairoff) {
    int tid  = blockIdx.x * 256 + threadIdx.x;
    int pair = pairoff + (tid >> 2);  // (b,d)
    int q    = tid & 3;               // state quarter
    int b    = pair >> 11;
    int d    = pair & 2047;

    float delta = __ldcs(g_delta + pair);
    float pole  = __ldcs(g_pole + pair);
    float xv    = __ldcs(X + pair);

    float4 hp = __ldcs((const float4*)Hprev + (size_t)pair * 4 + q);
    float4 ab = __ldg((const float4*)g_Abase + d * 4 + q);
    float4 bt = __ldg((const float4*)g_Bt + b * 4 + q);
    float4 ct = __ldg((const float4*)g_Ct + b * 4 + q);

    float dbx = delta * xv;
    float4 h;
    h.x = __expf(delta * (ab.x + pole)) * hp.x + dbx * bt.x;
    h.y = __expf(delta * (ab.y + pole)) * hp.y + dbx * bt.y;
    h.z = __expf(delta * (ab.z + pole)) * hp.z + dbx * bt.z;
    h.w = __expf(delta * (ab.w + pole)) * hp.w + dbx * bt.w;

    __stcs((float4*)Hout + (size_t)pair * 4 + q, h);

    float partial = h.x * ct.x + h.y * ct.y + h.z * ct.z + h.w * ct.w;
    partial += __shfl_xor_sync(0xffffffff, partial, 1);
    partial += __shfl_xor_sync(0xffffffff, partial, 2);
    if (q == 0) __stcs(Yout + pair, partial + __ldg(Dv + d) * xv);
}

// ---------------- launch: batch-split pipeline of GEMM and state ----------
extern "C" void kernel_launch(void* const* d_in, const int* in_sizes, int n_in,
                              void* d_out, int out_size) {
    const float* x      = (const float*)d_in[0];
    const float* h_prev = (const float*)d_in[1];
    const float* ev     = (const float*)d_in[2];
    const float* A_log  = (const float*)d_in[3];
    const float* Dv     = (const float*)d_in[4];
    const float* Wd     = (const float*)d_in[5];
    const float* bd     = (const float*)d_in[6];
    const float* We     = (const float*)d_in[7];
    const float* B_W1   = (const float*)d_in[8];
    const float* B_b1   = (const float*)d_in[9];
    const float* B_W2   = (const float*)d_in[10];
    const float* B_b2   = (const float*)d_in[11];
    const float* B_We   = (const float*)d_in[12];
    const float* A_We   = (const float*)d_in[13];
    const float* C_W    = (const float*)d_in[14];

    float* y_out = (float*)d_out;
    float* h_out = y_out + (size_t)BATCH * DMODEL;

    static cudaStream_t sB = nullptr;
    static cudaEvent_t  evG1 = nullptr, evS1 = nullptr;
    if (sB == nullptr) {
        cudaStreamCreateWithFlags(&sB, cudaStreamNonBlocking);
        cudaEventCreateWithFlags(&evG1, cudaEventDisableTiming);
        cudaEventCreateWithFlags(&evS1, cudaEventDisableTiming);
    }

    const int HALF_ROWS  = BATCH / 2;                      // 1024
    const int HALF_PAIRS = HALF_ROWS * DMODEL;             // pair offset
    const int STATE_BLKS = HALF_PAIRS * 4 / 256;           // 32768

    // prep chain (serial on main stream)
    k_prep<<<(BATCH * DMODEL / 4 + 255) / 256, 256>>>(x, Wd, ev, We);
    k_pole<<<dim3(BATCH / 32, DMODEL / 128), 256>>>(ev, A_We, A_log);
    k_small_p<<<dim3(BATCH / 32, 4), 256>>>(x, B_W1, C_W);
    k_small_f<<<BATCH / 8, 256>>>(ev, B_b1, B_W2, B_b2, B_We);

    // GEMM half 1 (batch rows 0..1023)
    k_gemm_delta<<<dim3(DMODEL / 128, HALF_ROWS / 128), 256>>>(bd, 0);
    cudaEventRecord(evG1, 0);

    // GEMM half 2 on main stream (concurrent with state half 1 on side)
    k_gemm_delta<<<dim3(DMODEL / 128, HALF_ROWS / 128), 256>>>(bd, HALF_ROWS);

    cudaStreamWaitEvent(sB, evG1, 0);
    k_state<<<STATE_BLKS, 256, 0, sB>>>(x, h_prev, Dv, y_out, h_out, 0);
    cudaEventRecord(evS1, sB);

    // state half 2 on main (after GEMM half 2)
    k_state<<<STATE_BLKS, 256>>>(x, h_prev, Dv, y_out, h_out, HALF_PAIRS);

    // join side stream back into main before capture ends
    cudaStreamWaitEvent(0, evS1, 0);
}

// round 17
// speedup vs baseline: 1.3890x; 1.0519x over previous
#include <cuda_runtime.h>
#include <cuda_bf16.h>
#include <cstdint>

#define BATCH   2048
#define DMODEL  2048
#define DSTATE  16
#define DEVENT  32

// ---------------- scratch ----------------
__device__ float g_delta[BATCH * DMODEL];   // delta_safe
__device__ float g_pole [BATCH * DMODEL];   // event @ A_We.T
__device__ float g_Abase[DMODEL * DSTATE];  // -exp(clip(A_log,-3,1))
__device__ float g_Bt   [BATCH * DSTATE];
__device__ float g_Ct   [BATCH * DSTATE];
__device__ float g_partH[4][BATCH * 2 * DSTATE];  // split-K partials of x@B_W1.T
__device__ float g_partC[4][BATCH * DSTATE];      // split-K partials of x@C_W.T
__device__ __nv_bfloat16 g_Xh [BATCH * DMODEL];   // bf16 copies for delta GEMM
__device__ __nv_bfloat16 g_Wdh[DMODEL * DMODEL];
__device__ __nv_bfloat16 g_Evh[BATCH * DEVENT];
__device__ __nv_bfloat16 g_Weh[DMODEL * DEVENT];

// ---------------- helpers ----------------
__device__ __forceinline__ void mma_bf16(float* c, const uint32_t* a, const uint32_t* b) {
    asm volatile(
        "mma.sync.aligned.m16n8k16.row.col.f32.bf16.bf16.f32 "
        "{%0,%1,%2,%3},{%4,%5,%6,%7},{%8,%9},{%0,%1,%2,%3};"
        : "+f"(c[0]), "+f"(c[1]), "+f"(c[2]), "+f"(c[3])
        : "r"(a[0]), "r"(a[1]), "r"(a[2]), "r"(a[3]), "r"(b[0]), "r"(b[1]));
}

__device__ __forceinline__ void ldsm4(uint32_t* r, uint32_t addr) {
    asm volatile(
        "ldmatrix.sync.aligned.m8n8.x4.shared.b16 {%0,%1,%2,%3}, [%4];"
        : "=r"(r[0]), "=r"(r[1]), "=r"(r[2]), "=r"(r[3]) : "r"(addr));
}

__device__ __forceinline__ void cp16(void* dst, const void* src) {
    uint32_t d = (uint32_t)__cvta_generic_to_shared(dst);
    asm volatile("cp.async.cg.shared.global [%0],[%1],16;\n" :: "r"(d), "l"(src));
}
__device__ __forceinline__ void cp_commit() {
    asm volatile("cp.async.commit_group;\n");
}

// ---------------- kernel 0: fp32 -> bf16 copies ----------------
__global__ __launch_bounds__(256) void k_prep(
    const float* __restrict__ X, const float* __restrict__ Wd,
    const float* __restrict__ Ev, const float* __restrict__ We) {
    int i4 = (blockIdx.x * 256 + threadIdx.x) * 4;   // grid covers 4M elements
    if (i4 < BATCH * DMODEL) {
        float4 vx = *(const float4*)(X + i4);
        float4 vw = *(const float4*)(Wd + i4);
        __nv_bfloat162* xo = (__nv_bfloat162*)(g_Xh + i4);
        __nv_bfloat162* wo = (__nv_bfloat162*)(g_Wdh + i4);
        xo[0] = __floats2bfloat162_rn(vx.x, vx.y);
        xo[1] = __floats2bfloat162_rn(vx.z, vx.w);
        wo[0] = __floats2bfloat162_rn(vw.x, vw.y);
        wo[1] = __floats2bfloat162_rn(vw.z, vw.w);
    }
    if (i4 < BATCH * DEVENT) {
        float4 ve = *(const float4*)(Ev + i4);
        float4 vq = *(const float4*)(We + i4);
        __nv_bfloat162* eo = (__nv_bfloat162*)(g_Evh + i4);
        __nv_bfloat162* qo = (__nv_bfloat162*)(g_Weh + i4);
        eo[0] = __floats2bfloat162_rn(ve.x, ve.y);
        eo[1] = __floats2bfloat162_rn(ve.z, ve.w);
        qo[0] = __floats2bfloat162_rn(vq.x, vq.y);
        qo[1] = __floats2bfloat162_rn(vq.z, vq.w);
    }
}

// ---------------- kernel 1: pole = event @ A_We.T (+ A_base fold) ---------
__global__ __launch_bounds__(256) void k_pole(const float* __restrict__ Ev,
                                              const float* __restrict__ A_We,
                                              const float* __restrict__ A_log) {
    __shared__ float Es[32][33];
    __shared__ float Ws[128][33];
    int t  = threadIdx.x;
    int b0 = blockIdx.x * 32;
    int d0 = blockIdx.y * 128;

    if (blockIdx.y == 0) {
        int i = (blockIdx.x * 256 + t) * 2;
#pragma unroll
        for (int e = 0; e < 2; ++e) {
            float a = A_log[i + e];
            a = fminf(fmaxf(a, -3.0f), 1.0f);
            g_Abase[i + e] = -__expf(a);
        }
    }

    {
        int idx = t;
        int r = idx >> 3, c4 = idx & 7;
        float4 v = *(const float4*)(Ev + (size_t)(b0 + r) * DEVENT + c4 * 4);
        Es[r][c4 * 4 + 0] = v.x; Es[r][c4 * 4 + 1] = v.y;
        Es[r][c4 * 4 + 2] = v.z; Es[r][c4 * 4 + 3] = v.w;
    }
#pragma unroll
    for (int i = 0; i < 4; ++i) {
        int idx = t + i * 256;
        int r = idx >> 3, c4 = idx & 7;
        float4 v = *(const float4*)(A_We + (size_t)(d0 + r) * DEVENT + c4 * 4);
        Ws[r][c4 * 4 + 0] = v.x; Ws[r][c4 * 4 + 1] = v.y;
        Ws[r][c4 * 4 + 2] = v.z; Ws[r][c4 * 4 + 3] = v.w;
    }
    __syncthreads();

    int d_sub = t & 127;
    int half  = t >> 7;
    for (int bs = half; bs < 32; bs += 2) {
        float acc = 0.0f;
#pragma unroll
        for (int e = 0; e < 32; ++e) acc += Es[bs][e] * Ws[d_sub][e];
        g_pole[(size_t)(b0 + bs) * DMODEL + d0 + d_sub] = acc;
    }
}

// ---------------- kernel 2a: split-K partials of x@B_W1.T and x@C_W.T -----
__global__ __launch_bounds__(256) void k_small_p(
    const float* __restrict__ X,
    const float* __restrict__ B_W1, const float* __restrict__ C_W) {
    __shared__ float Xs[32][132];
    __shared__ float Ws[48][132];

    int t    = threadIdx.x;
    int b0   = blockIdx.x * 32;
    int kb   = blockIdx.y * 512;
    int row  = t >> 3;
    int tcol = t & 7;

    float accH[4] = {0, 0, 0, 0};
    float accC[2] = {0, 0};

    for (int kc = kb; kc < kb + 512; kc += 128) {
#pragma unroll
        for (int i = 0; i < 4; ++i) {
            int idx = t + i * 256;
            int r = idx >> 5, c4 = idx & 31;
            float4 v = *(const float4*)(X + (size_t)(b0 + r) * DMODEL + kc + c4 * 4);
            *(float4*)(&Xs[r][c4 * 4]) = v;
        }
#pragma unroll
        for (int i = 0; i < 6; ++i) {
            int idx = t + i * 256;
            int r = idx >> 5, c4 = idx & 31;
            const float* src = (r < 32)
                ? (B_W1 + (size_t)r * DMODEL + kc + c4 * 4)
                : (C_W + (size_t)(r - 32) * DMODEL + kc + c4 * 4);
            float4 v = *(const float4*)src;
            *(float4*)(&Ws[r][c4 * 4]) = v;
        }
        __syncthreads();
#pragma unroll 4
        for (int kk = 0; kk < 128; ++kk) {
            float xv = Xs[row][kk];
#pragma unroll
            for (int i = 0; i < 4; ++i) accH[i] += xv * Ws[tcol + 8 * i][kk];
#pragma unroll
            for (int i = 0; i < 2; ++i) accC[i] += xv * Ws[32 + tcol + 8 * i][kk];
        }
        __syncthreads();
    }

    int ks = blockIdx.y;
#pragma unroll
    for (int i = 0; i < 4; ++i)
        g_partH[ks][(size_t)(b0 + row) * 32 + tcol + 8 * i] = accH[i];
#pragma unroll
    for (int i = 0; i < 2; ++i)
        g_partC[ks][(size_t)(b0 + row) * DSTATE + tcol + 8 * i] = accC[i];
}

// ---------------- kernel 2b: combine partials, smem-staged weights --------
__global__ __launch_bounds__(256) void k_small_f(
    const float* __restrict__ Ev,
    const float* __restrict__ B_b1, const float* __restrict__ B_W2,
    const float* __restrict__ B_b2, const float* __restrict__ B_We) {
    __shared__ float Hs[8][33];
    __shared__ float W2s[16][32];   // B_W2  (512 floats)
    __shared__ float Wes[16][32];   // B_We  (512 floats)
    __shared__ float Evs[8][32];

    int t   = threadIdx.x;
    int b0  = blockIdx.x * 8;
    int row = t >> 5, col = t & 31;   // 8 rows x 32 cols

    // stage weights: 512 floats each, 256 threads -> 2 per thread
#pragma unroll
    for (int i = 0; i < 2; ++i) {
        int idx = t + i * 256;
        ((float*)W2s)[idx] = B_W2[idx];
        ((float*)Wes)[idx] = B_We[idx];
    }
    Evs[row][col] = Ev[(size_t)(b0 + row) * DEVENT + col];

    {
        size_t off = (size_t)(b0 + row) * 32 + col;
        float z = g_partH[0][off] + g_partH[1][off]
                + g_partH[2][off] + g_partH[3][off] + B_b1[col];
        Hs[row][col] = z / (1.0f + __expf(-z));
    }
    if (t < 128) {
        int r = t >> 4, n = t & 15;
        size_t off = (size_t)(b0 + r) * DSTATE + n;
        g_Ct[off] = g_partC[0][off] + g_partC[1][off]
                  + g_partC[2][off] + g_partC[3][off];
    }
    __syncthreads();

    if (t < 128) {
        int r = t >> 4, n = t & 15;
        float acc = B_b2[n];
#pragma unroll
        for (int j = 0; j < 32; ++j) acc += Hs[r][j] * W2s[n][j];
#pragma unroll
        for (int e = 0; e < 32; ++e) acc += Evs[r][e] * Wes[n][e];
        g_Bt[(size_t)(b0 + r) * DSTATE + n] = acc;
    }
}

// ---------------- kernel 3: delta GEMM in bf16 (m16n8k16), full grid ------
#define STGB 10240   // bytes per operand stage

__global__ __launch_bounds__(256) void k_gemm_delta(const float* __restrict__ bd) {
    __shared__ char smem[4 * STGB];   // [2 stages][A], [2 stages][B]

    const int tid  = threadIdx.x;
    const int row0 = blockIdx.y * 128;   // batch
    const int col0 = blockIdx.x * 128;   // d_model
    const int wid  = tid >> 5, lane = tid & 31;
    const int g    = lane >> 2, tg = lane & 3;
    const int wm0  = (wid & 1) * 64;
    const int wn0  = (wid >> 1) * 32;

    const uint32_t sAbase = (uint32_t)__cvta_generic_to_shared(smem);
    const uint32_t sBbase = sAbase + 2 * STGB;

    const int aRow  = wm0 + ((lane >> 3) & 1) * 8 + (lane & 7);
    const int aColB = (lane >> 4) * 16;
    const int bRow  = wn0 + (lane >> 4) * 8 + (lane & 7);
    const int bColB = ((lane >> 3) & 1) * 16;

    float acc[4][4][4];
#pragma unroll
    for (int mi = 0; mi < 4; ++mi)
#pragma unroll
        for (int ni = 0; ni < 4; ++ni)
#pragma unroll
            for (int r = 0; r < 4; ++r) acc[mi][ni][r] = 0.0f;

    auto load_tile = [&](int kt, int s) {
        const __nv_bfloat16 *srcA, *srcB;
        int lda, ldb;
        if (kt < 64) {
            srcA = g_Xh  + (size_t)row0 * DMODEL + kt * 32; lda = DMODEL;
            srcB = g_Wdh + (size_t)col0 * DMODEL + kt * 32; ldb = DMODEL;
        } else {
            srcA = g_Evh + (size_t)row0 * DEVENT; lda = DEVENT;
            srcB = g_Weh + (size_t)col0 * DEVENT; ldb = DEVENT;
        }
        char* as = smem + s * STGB;
        char* bs = smem + 2 * STGB + s * STGB;
#pragma unroll
        for (int i = 0; i < 2; ++i) {
            int idx = tid + i * 256;     // 512 16B chunks per operand
            int m = idx >> 2, c = idx & 3;
            cp16(as + m * 80 + c * 16, srcA + (size_t)m * lda + c * 8);
            cp16(bs + m * 80 + c * 16, srcB + (size_t)m * ldb + c * 8);
        }
        cp_commit();
    };

    load_tile(0, 0);

    for (int kt = 0; kt < 65; ++kt) {
        asm volatile("cp.async.wait_group 0;\n");
        __syncthreads();
        if (kt < 64) load_tile(kt + 1, (kt + 1) & 1);

        const uint32_t sa = sAbase + (kt & 1) * STGB;
        const uint32_t sb = sBbase + (kt & 1) * STGB;
#pragma unroll
        for (int ks = 0; ks < 2; ++ks) {
            uint32_t a[4][4], b[4][2];
#pragma unroll
            for (int mi = 0; mi < 4; ++mi)
                ldsm4(a[mi], sa + (uint32_t)((aRow + mi * 16) * 80
                                             + ks * 32 + aColB));
#pragma unroll
            for (int np = 0; np < 2; ++np) {
                uint32_t r4[4];
                ldsm4(r4, sb + (uint32_t)((bRow + np * 16) * 80
                                          + ks * 32 + bColB));
                b[np * 2 + 0][0] = r4[0]; b[np * 2 + 0][1] = r4[1];
                b[np * 2 + 1][0] = r4[2]; b[np * 2 + 1][1] = r4[3];
            }
#pragma unroll
            for (int mi = 0; mi < 4; ++mi)
#pragma unroll
                for (int ni = 0; ni < 4; ++ni)
                    mma_bf16(acc[mi][ni], a[mi], b[ni]);
        }
    }

    // epilogue: delta_safe = min(softplus(z + bd), 2)
#pragma unroll
    for (int mi = 0; mi < 4; ++mi) {
        int rbase = row0 + wm0 + mi * 16 + g;
#pragma unroll
        for (int ni = 0; ni < 4; ++ni) {
            int cbase = col0 + wn0 + ni * 8 + tg * 2;
#pragma unroll
            for (int r = 0; r < 4; ++r) {
                int bb = rbase + (r >> 1) * 8;
                int dd = cbase + (r & 1);
                float z = acc[mi][ni][r] + __ldg(&bd[dd]);
                float sp = fmaxf(z, 0.0f) + __logf(1.0f + __expf(-fabsf(z)));
                g_delta[(size_t)bb * DMODEL + dd] = fminf(sp, 2.0f);
            }
        }
    }
}

// ---------------- kernel 4: state update, streaming-hinted ----------------
__global__ __launch_bounds__(256) void k_state(
    const float* __restrict__ X, const float* __restrict__ Hprev,
    const float* __restrict__ Dv, float* __restrict__ Yout,
    float* __restrict__ Hout) {
    int tid  = blockIdx.x * 256 + threadIdx.x;
    int pair = tid >> 2;          // (b,d)
    int q    = tid & 3;           // state quarter
    int b    = pair >> 11;
    int d    = pair & 2047;

    float delta = __ldcs(g_delta + pair);
    float pole  = __ldcs(g_pole + pair);
    float xv    = __ldcs(X + pair);

    float4 hp = __ldcs((const float4*)Hprev + (size_t)pair * 4 + q);
    float4 ab = __ldg((const float4*)g_Abase + d * 4 + q);
    float4 bt = __ldg((const float4*)g_Bt + b * 4 + q);
    float4 ct = __ldg((const float4*)g_Ct + b * 4 + q);

    float dbx = delta * xv;
    float4 h;
    h.x = __expf(delta * (ab.x + pole)) * hp.x + dbx * bt.x;
    h.y = __expf(delta * (ab.y + pole)) * hp.y + dbx * bt.y;
    h.z = __expf(delta * (ab.z + pole)) * hp.z + dbx * bt.z;
    h.w = __expf(delta * (ab.w + pole)) * hp.w + dbx * bt.w;

    __stcs((float4*)Hout + (size_t)pair * 4 + q, h);

    float partial = h.x * ct.x + h.y * ct.y + h.z * ct.z + h.w * ct.w;
    partial += __shfl_xor_sync(0xffffffff, partial, 1);
    partial += __shfl_xor_sync(0xffffffff, partial, 2);
    if (q == 0) __stcs(Yout + pair, partial + __ldg(Dv + d) * xv);
}

// ---------------- launch: prep side-chain overlapped with bf16+GEMM -------
extern "C" void kernel_launch(void* const* d_in, const int* in_sizes, int n_in,
                              void* d_out, int out_size) {
    const float* x      = (const float*)d_in[0];
    const float* h_prev = (const float*)d_in[1];
    const float* ev     = (const float*)d_in[2];
    const float* A_log  = (const float*)d_in[3];
    const float* Dv     = (const float*)d_in[4];
    const float* Wd     = (const float*)d_in[5];
    const float* bd     = (const float*)d_in[6];
    const float* We     = (const float*)d_in[7];
    const float* B_W1   = (const float*)d_in[8];
    const float* B_b1   = (const float*)d_in[9];
    const float* B_W2   = (const float*)d_in[10];
    const float* B_b2   = (const float*)d_in[11];
    const float* B_We   = (const float*)d_in[12];
    const float* A_We   = (const float*)d_in[13];
    const float* C_W    = (const float*)d_in[14];

    float* y_out = (float*)d_out;
    float* h_out = y_out + (size_t)BATCH * DMODEL;

    static cudaStream_t sB = nullptr;
    static cudaEvent_t  evFork = nullptr, evSide = nullptr;
    if (sB == nullptr) {
        cudaStreamCreateWithFlags(&sB, cudaStreamNonBlocking);
        cudaEventCreateWithFlags(&evFork, cudaEventDisableTiming);
        cudaEventCreateWithFlags(&evSide, cudaEventDisableTiming);
    }

    // fork side stream
    cudaEventRecord(evFork, 0);
    cudaStreamWaitEvent(sB, evFork, 0);

    // side chain: pole -> small_p -> small_f (feeds only k_state)
    k_pole<<<dim3(BATCH / 32, DMODEL / 128), 256, 0, sB>>>(ev, A_We, A_log);
    k_small_p<<<dim3(BATCH / 32, 4), 256, 0, sB>>>(x, B_W1, C_W);
    k_small_f<<<BATCH / 8, 256, 0, sB>>>(ev, B_b1, B_W2, B_b2, B_We);
    cudaEventRecord(evSide, sB);

    // main chain: bf16 convert -> full-grid GEMM
    k_prep<<<(BATCH * DMODEL / 4 + 255) / 256, 256>>>(x, Wd, ev, We);
    k_gemm_delta<<<dim3(DMODEL / 128, BATCH / 128), 256>>>(bd);

    // join, then state
    cudaStreamWaitEvent(0, evSide, 0);
    k_state<<<(BATCH * DMODEL * 4) / 256, 256>>>(x, h_prev, Dv, y_out, h_out);
}